// round 9
// baseline (speedup 1.0000x reference)
#include <cuda_runtime.h>
#include <cuda_bf16.h>

#define Bn 64
#define Sn 1024
#define Vn 32000
#define Dn 1024
#define Hn 1024
#define En 1024
#define An 1024

// ---------------- scratch (no allocs allowed) ----------------
__device__ float g_q[Bn * An];
__device__ float g_score[Bn * Sn];
__device__ float g_xh0[Bn * 3072];   // [embedded(1024), context(1024), h0[0](1024)]
__device__ float g_xh1[Bn * 2048];   // [h1(1024), h0[1](1024)]
__device__ float g_gates[Bn * 4 * Hn];

// ---------------- helpers ----------------
__device__ __forceinline__ unsigned f2tf(float f) {
    unsigned u;
    asm("cvt.rna.tf32.f32 %0, %1;" : "=r"(u) : "f"(f));
    return u;
}

__device__ __forceinline__ uint4 cvt4(float4 v) {
    uint4 o;
    o.x = f2tf(v.x); o.y = f2tf(v.y); o.z = f2tf(v.z); o.w = f2tf(v.w);
    return o;
}

__device__ __forceinline__ void mma_tf32(float* c, const unsigned* a, const unsigned* b) {
    asm volatile(
        "mma.sync.aligned.m16n8k8.row.col.f32.tf32.tf32.f32 "
        "{%0,%1,%2,%3}, {%4,%5,%6,%7}, {%8,%9}, {%0,%1,%2,%3};"
        : "+f"(c[0]), "+f"(c[1]), "+f"(c[2]), "+f"(c[3])
        : "r"(a[0]), "r"(a[1]), "r"(a[2]), "r"(a[3]), "r"(b[0]), "r"(b[1]));
}

__device__ __forceinline__ void ldsm4(unsigned* r, unsigned addr) {
    asm volatile("ldmatrix.sync.aligned.m8n8.x4.shared.b16 {%0,%1,%2,%3}, [%4];"
                 : "=r"(r[0]), "=r"(r[1]), "=r"(r[2]), "=r"(r[3]) : "r"(addr));
}

// ---------------- embedding gather + h staging ----------------
__global__ void embed_kernel(const int* __restrict__ input_step,
                             const float* __restrict__ emb,
                             const float* __restrict__ h0,
                             float* __restrict__ xh0,
                             float* __restrict__ xh1) {
    int b = blockIdx.x;
    int row = input_step[b];
    const float* src = emb + (size_t)row * Dn;
    for (int d = threadIdx.x; d < Dn; d += blockDim.x) {
        xh0[(size_t)b * 3072 + d] = src[d];                    // embedded
        xh0[(size_t)b * 3072 + 2048 + d] = h0[b * Hn + d];     // h0[0]
        xh1[(size_t)b * 2048 + 1024 + d] = h0[Bn * Hn + b * Hn + d];  // h0[1]
    }
}

// ---------------- tf32 TC GEMM with split-K weights ----------------
// C[64,N] = A[64,Ktot] @ [W1 (N x K1); W2 (N x Ktot-K1)]^T + bias + bias2
// BM=64, BN=64, BK=32, 128 threads = 4 warps (2 m x 2 n), warp tile 32x32.
__global__ __launch_bounds__(128) void gemm_nt_tc2(
        const float* __restrict__ Amat, int Ktot,
        const float* __restrict__ W1, int K1, const float* __restrict__ W2,
        const float* __restrict__ bias, const float* __restrict__ bias2,
        float* __restrict__ Cmat, int N) {
    __shared__ char gsm[2][16384];  // per stage: A 8KB + W 8KB
    unsigned sbase = (unsigned)__cvta_generic_to_shared(gsm);

    int tid = threadIdx.x;
    int w = tid >> 5, lane = tid & 31, g = lane >> 2, tig = lane & 3;
    int n0 = blockIdx.x * 64;
    int mb = (w & 1) * 32;
    int nb = (w >> 1) * 32;
    int K2 = Ktot - K1;

    int lr = tid >> 3;       // 0..15
    int lc16 = tid & 7;      // 16B column

    int rA = mb + (lane & 15);
    int akh = (lane >> 4) & 1;
    unsigned aRow0 = rA * 128, aRow1 = (rA + 16) * 128;
    int am = rA & 7;
    int rB = nb + ((lane >> 1) & 8) + (lane & 7);
    int bkh = (lane >> 3) & 1;
    unsigned bRow0 = rB * 128, bRow1 = (rB + 16) * 128;
    int bm = rB & 7;

    float acc[2][4][4];
#pragma unroll
    for (int mt = 0; mt < 2; mt++)
#pragma unroll
        for (int nf = 0; nf < 4; nf++)
#pragma unroll
            for (int r = 0; r < 4; r++) acc[mt][nf][r] = 0.f;

#define WROW(row, k) ((k) < K1 ? W1 + (size_t)(row) * K1 + (k) \
                               : W2 + (size_t)(row) * K2 + ((k) - K1))

    float4 aReg[4], wReg[4];
#pragma unroll
    for (int i = 0; i < 4; i++) {
        int row = lr + 16 * i;
        aReg[i] = *(const float4*)&Amat[(size_t)row * Ktot + lc16 * 4];
        wReg[i] = *(const float4*)(WROW(n0 + row, 0) + lc16 * 4);
    }

    int st = 0;
    for (int k0 = 0; k0 < Ktot; k0 += 32) {
#pragma unroll
        for (int i = 0; i < 4; i++) {
            int row = lr + 16 * i;
            unsigned off = row * 128 + (unsigned)((lc16 ^ (row & 7)) << 4);
            *(uint4*)(gsm[st] + off) = cvt4(aReg[i]);
            *(uint4*)(gsm[st] + 8192 + off) = cvt4(wReg[i]);
        }
        __syncthreads();

        if (k0 + 32 < Ktot) {
#pragma unroll
            for (int i = 0; i < 4; i++) {
                int row = lr + 16 * i;
                aReg[i] = *(const float4*)&Amat[(size_t)row * Ktot + k0 + 32 + lc16 * 4];
                wReg[i] = *(const float4*)(WROW(n0 + row, k0 + 32) + lc16 * 4);
            }
        }

        unsigned Ab = sbase + st * 16384;
        unsigned Wb = Ab + 8192;
#pragma unroll
        for (int ks = 0; ks < 4; ks++) {
            unsigned a0[4], a1[4], b0[4], b1[4];
            unsigned acol = ((unsigned)(ks * 2 + akh) ^ am) << 4;
            unsigned bcol = ((unsigned)(ks * 2 + bkh) ^ bm) << 4;
            ldsm4(a0, Ab + aRow0 + acol);
            ldsm4(a1, Ab + aRow1 + acol);
            ldsm4(b0, Wb + bRow0 + bcol);
            ldsm4(b1, Wb + bRow1 + bcol);
            mma_tf32(acc[0][0], a0, b0);
            mma_tf32(acc[0][1], a0, b0 + 2);
            mma_tf32(acc[1][0], a1, b0);
            mma_tf32(acc[1][1], a1, b0 + 2);
            mma_tf32(acc[0][2], a0, b1);
            mma_tf32(acc[0][3], a0, b1 + 2);
            mma_tf32(acc[1][2], a1, b1);
            mma_tf32(acc[1][3], a1, b1 + 2);
        }
        __syncthreads();
        st ^= 1;
    }
#undef WROW

#pragma unroll
    for (int mt = 0; mt < 2; mt++) {
        int m0i = mb + mt * 16 + g;
        int m1i = m0i + 8;
#pragma unroll
        for (int nf = 0; nf < 4; nf++) {
            int n = n0 + nb + nf * 8 + 2 * tig;
            float badd0 = 0.f, badd1 = 0.f;
            if (bias)  { badd0 += bias[n];  badd1 += bias[n + 1]; }
            if (bias2) { badd0 += bias2[n]; badd1 += bias2[n + 1]; }
            Cmat[(size_t)m0i * N + n]     = acc[mt][nf][0] + badd0;
            Cmat[(size_t)m0i * N + n + 1] = acc[mt][nf][1] + badd1;
            Cmat[(size_t)m1i * N + n]     = acc[mt][nf][2] + badd0;
            Cmat[(size_t)m1i * N + n + 1] = acc[mt][nf][3] + badd1;
        }
    }
}

// ---------------- score init ----------------
__global__ void score_init_kernel(const float* __restrict__ bva, float* __restrict__ score) {
    int i = blockIdx.x * blockDim.x + threadIdx.x;
    if (i < Bn * Sn) score[i] = bva[0];
}

// ---------------- fused attention score GEMM ----------------
// BM=128, BN=128, BK=32, 512 threads (16 warps: 4m x 4n, warp tile 32x32).
// LDG->cvt.rna->STS staging, double-buffered with register prefetch (no pre-convert).
// grid: (A/128 = 8, BS/128 = 512), x fastest -> enc tile L2 reuse.
__global__ __launch_bounds__(512) void score_gemm_mma(
        const float* __restrict__ enc, const float* __restrict__ wae,
        const float* __restrict__ ba_e, const float* __restrict__ q,
        const float* __restrict__ va, float* __restrict__ score) {
    __shared__ char gsm[2][32768];  // per stage: A 16KB + W 16KB
    __shared__ float qb[128];
    __shared__ float vas[128];
    unsigned sbase = (unsigned)__cvta_generic_to_shared(gsm);

    int tid = threadIdx.x;
    int w = tid >> 5, lane = tid & 31, g = lane >> 2, tig = lane & 3;
    int n0 = blockIdx.x * 128;
    int m0 = blockIdx.y * 128;
    int b = m0 >> 10;
    int mb = (w >> 2) * 32;
    int nb = (w & 3) * 32;

    if (tid < 128) {
        qb[tid]  = q[b * An + n0 + tid] + ba_e[n0 + tid];
        vas[tid] = va[n0 + tid];
    }

    int lr = tid >> 3;       // 0..63
    int lc16 = tid & 7;      // 16B column
    const float* encp = enc + (size_t)m0 * En;
    const float* waep = wae + (size_t)n0 * En;

    int rA = mb + (lane & 15);
    int akh = (lane >> 4) & 1;
    unsigned aRow0 = rA * 128, aRow1 = (rA + 16) * 128;
    int am = rA & 7;
    int rB = nb + ((lane >> 1) & 8) + (lane & 7);
    int bkh = (lane >> 3) & 1;
    unsigned bRow0 = rB * 128, bRow1 = (rB + 16) * 128;
    int bm = rB & 7;

    float acc[2][4][4];
#pragma unroll
    for (int mt = 0; mt < 2; mt++)
#pragma unroll
        for (int nf = 0; nf < 4; nf++)
#pragma unroll
            for (int r = 0; r < 4; r++) acc[mt][nf][r] = 0.f;

    float4 aReg[2], wReg[2];
#pragma unroll
    for (int i = 0; i < 2; i++) {
        int row = lr + 64 * i;
        aReg[i] = *(const float4*)&encp[(size_t)row * En + lc16 * 4];
        wReg[i] = *(const float4*)&waep[(size_t)row * En + lc16 * 4];
    }

    int st = 0;
    for (int k0 = 0; k0 < En; k0 += 32) {
#pragma unroll
        for (int i = 0; i < 2; i++) {
            int row = lr + 64 * i;
            unsigned off = row * 128 + (unsigned)((lc16 ^ (row & 7)) << 4);
            *(uint4*)(gsm[st] + off) = cvt4(aReg[i]);
            *(uint4*)(gsm[st] + 16384 + off) = cvt4(wReg[i]);
        }
        __syncthreads();

        if (k0 + 32 < En) {
#pragma unroll
            for (int i = 0; i < 2; i++) {
                int row = lr + 64 * i;
                aReg[i] = *(const float4*)&encp[(size_t)row * En + k0 + 32 + lc16 * 4];
                wReg[i] = *(const float4*)&waep[(size_t)row * En + k0 + 32 + lc16 * 4];
            }
        }

        unsigned Ab = sbase + st * 32768;
        unsigned Wb = Ab + 16384;
#pragma unroll
        for (int ks = 0; ks < 4; ks++) {
            unsigned a0[4], a1[4], b0[4], b1[4];
            unsigned acol = ((unsigned)(ks * 2 + akh) ^ am) << 4;
            unsigned bcol = ((unsigned)(ks * 2 + bkh) ^ bm) << 4;
            ldsm4(a0, Ab + aRow0 + acol);
            ldsm4(a1, Ab + aRow1 + acol);
            ldsm4(b0, Wb + bRow0 + bcol);
            ldsm4(b1, Wb + bRow1 + bcol);
            mma_tf32(acc[0][0], a0, b0);
            mma_tf32(acc[0][1], a0, b0 + 2);
            mma_tf32(acc[1][0], a1, b0);
            mma_tf32(acc[1][1], a1, b0 + 2);
            mma_tf32(acc[0][2], a0, b1);
            mma_tf32(acc[0][3], a0, b1 + 2);
            mma_tf32(acc[1][2], a1, b1);
            mma_tf32(acc[1][3], a1, b1 + 2);
        }
        __syncthreads();
        st ^= 1;
    }

    // epilogue: tanh + va-weighted row reduction
#pragma unroll
    for (int mt = 0; mt < 2; mt++) {
        float sumlo = 0.f, sumhi = 0.f;
#pragma unroll
        for (int nf = 0; nf < 4; nf++) {
            int nl = nb + nf * 8 + 2 * tig;
            float q0 = qb[nl], q1 = qb[nl + 1];
            float v0 = vas[nl], v1 = vas[nl + 1];
            sumlo += v0 * tanhf(acc[mt][nf][0] + q0) + v1 * tanhf(acc[mt][nf][1] + q1);
            sumhi += v0 * tanhf(acc[mt][nf][2] + q0) + v1 * tanhf(acc[mt][nf][3] + q1);
        }
        sumlo += __shfl_xor_sync(0xffffffffu, sumlo, 1);
        sumlo += __shfl_xor_sync(0xffffffffu, sumlo, 2);
        sumhi += __shfl_xor_sync(0xffffffffu, sumhi, 1);
        sumhi += __shfl_xor_sync(0xffffffffu, sumhi, 2);
        if (tig == 0) {
            int r = m0 + mb + mt * 16 + g;
            atomicAdd(&score[r], sumlo);
            atomicAdd(&score[r + 8], sumhi);
        }
    }
}

// ---------------- softmax ----------------
__global__ void softmax_kernel(const float* __restrict__ score, float* __restrict__ attn) {
    __shared__ float sh[Sn];
    __shared__ float red[256];
    int b = blockIdx.x;
    int tid = threadIdx.x;

    float lmax = -3.4e38f;
    for (int s = tid; s < Sn; s += 256) {
        float v = score[b * Sn + s];
        sh[s] = v;
        lmax = fmaxf(lmax, v);
    }
    red[tid] = lmax;
    __syncthreads();
    for (int off = 128; off > 0; off >>= 1) {
        if (tid < off) red[tid] = fmaxf(red[tid], red[tid + off]);
        __syncthreads();
    }
    float m = red[0];
    __syncthreads();

    float lsum = 0.f;
    for (int s = tid; s < Sn; s += 256) {
        float e = expf(sh[s] - m);
        sh[s] = e;
        lsum += e;
    }
    red[tid] = lsum;
    __syncthreads();
    for (int off = 128; off > 0; off >>= 1) {
        if (tid < off) red[tid] += red[tid + off];
        __syncthreads();
    }
    float inv = 1.f / red[0];
    __syncthreads();

    for (int s = tid; s < Sn; s += 256) attn[b * Sn + s] = sh[s] * inv;
}

// ---------------- context = attn @ enc (writes into xh0 middle slot) ----------------
__global__ void context_kernel(const float* __restrict__ enc,
                               const float* __restrict__ attn,
                               float* __restrict__ xh0) {
    __shared__ float w[Sn];
    int b = blockIdx.x;
    int e = blockIdx.y * 256 + threadIdx.x;
    for (int s = threadIdx.x; s < Sn; s += 256) w[s] = attn[b * Sn + s];
    __syncthreads();
    const float* ep = enc + (size_t)b * Sn * En + e;
    float acc = 0.f;
#pragma unroll 8
    for (int s = 0; s < Sn; s++) acc += w[s] * ep[(size_t)s * En];
    xh0[(size_t)b * 3072 + 1024 + e] = acc;
}

// ---------------- LSTM pointwise (optionally stages h into concat buffer) ----------------
__global__ void lstm_pointwise(const float* __restrict__ gates,
                               const float* __restrict__ cprev,
                               float* __restrict__ hout,
                               float* __restrict__ cout,
                               float* __restrict__ hcopy, int hstride) {
    int idx = blockIdx.x * 256 + threadIdx.x;
    if (idx >= Bn * Hn) return;
    int b = idx >> 10;
    int h = idx & 1023;
    const float* g = gates + (size_t)b * 4 * Hn;
    float ig = 1.f / (1.f + expf(-g[h]));
    float fg = 1.f / (1.f + expf(-g[Hn + h]));
    float gg = tanhf(g[2 * Hn + h]);
    float og = 1.f / (1.f + expf(-g[3 * Hn + h]));
    float c = fg * cprev[idx] + ig * gg;
    float hv = og * tanhf(c);
    hout[idx] = hv;
    cout[idx] = c;
    if (hcopy) hcopy[(size_t)b * hstride + h] = hv;
}

// ---------------- launcher ----------------
extern "C" void kernel_launch(void* const* d_in, const int* in_sizes, int n_in,
                              void* d_out, int out_size) {
    const int*   input_step = (const int*)d_in[0];
    const float* h0    = (const float*)d_in[1];
    const float* c0    = (const float*)d_in[2];
    const float* enc   = (const float*)d_in[3];
    const float* emb   = (const float*)d_in[4];
    const float* Wa_h  = (const float*)d_in[5];
    const float* ba_h  = (const float*)d_in[6];
    const float* Wa_e  = (const float*)d_in[7];
    const float* ba_e  = (const float*)d_in[8];
    const float* va    = (const float*)d_in[9];
    const float* bva   = (const float*)d_in[10];
    const float* Wih0  = (const float*)d_in[11];
    const float* Whh0  = (const float*)d_in[12];
    const float* bih0  = (const float*)d_in[13];
    const float* bhh0  = (const float*)d_in[14];
    const float* Wih1  = (const float*)d_in[15];
    const float* Whh1  = (const float*)d_in[16];
    const float* bih1  = (const float*)d_in[17];
    const float* bhh1  = (const float*)d_in[18];
    const float* Wout  = (const float*)d_in[19];
    const float* bout  = (const float*)d_in[20];

    float* out = (float*)d_out;
    float* out_logits = out;
    float* out_h      = out_logits + Bn * Vn;
    float* out_c      = out_h + 2 * Bn * Hn;
    float* out_attn   = out_c + 2 * Bn * Hn;

    float* q_buf;     cudaGetSymbolAddress((void**)&q_buf, g_q);
    float* score_buf; cudaGetSymbolAddress((void**)&score_buf, g_score);
    float* xh0;       cudaGetSymbolAddress((void**)&xh0, g_xh0);
    float* xh1;       cudaGetSymbolAddress((void**)&xh1, g_xh1);
    float* gates_buf; cudaGetSymbolAddress((void**)&gates_buf, g_gates);

    // 1. embedding gather + h0 staging
    embed_kernel<<<Bn, 256>>>(input_step, emb, h0, xh0, xh1);

    // 2. q = h0[1] @ Wa_h^T + ba_h
    gemm_nt_tc2<<<An / 64, 128>>>(h0 + Bn * Hn, Hn, Wa_h, Hn, nullptr,
                                  ba_h, nullptr, q_buf, An);

    // 3. fused tf32 score GEMM (in-kernel cvt, no pre-convert pass)
    score_init_kernel<<<(Bn * Sn + 255) / 256, 256>>>(bva, score_buf);
    {
        dim3 grid(An / 128, Bn * Sn / 128);
        score_gemm_mma<<<grid, 512>>>(enc, Wa_e, ba_e, q_buf, va, score_buf);
    }

    // 4. softmax
    softmax_kernel<<<Bn, 256>>>(score_buf, out_attn);

    // 5. context -> xh0[:, 1024:2048]
    {
        dim3 grid(Bn, En / 256);
        context_kernel<<<grid, 256>>>(enc, out_attn, xh0);
    }

    // 6. LSTM layer 0: gates = [x, h0[0]] @ [Wih0; Whh0]^T + biases
    gemm_nt_tc2<<<4 * Hn / 64, 128>>>(xh0, 3072, Wih0, Dn + En, Whh0,
                                      bih0, bhh0, gates_buf, 4 * Hn);
    lstm_pointwise<<<(Bn * Hn + 255) / 256, 256>>>(gates_buf, c0, out_h, out_c,
                                                   xh1, 2048);

    // 7. LSTM layer 1: gates = [h1, h0[1]] @ [Wih1; Whh1]^T + biases
    gemm_nt_tc2<<<4 * Hn / 64, 128>>>(xh1, 2048, Wih1, Hn, Whh1,
                                      bih1, bhh1, gates_buf, 4 * Hn);
    lstm_pointwise<<<(Bn * Hn + 255) / 256, 256>>>(gates_buf, c0 + Bn * Hn,
                                                   out_h + Bn * Hn, out_c + Bn * Hn,
                                                   nullptr, 0);

    // 8. logits = h2 @ Wout^T + bout
    gemm_nt_tc2<<<Vn / 64, 128>>>(out_h + Bn * Hn, Hn, Wout, Hn, nullptr,
                                  bout, nullptr, out_logits, Vn);
}

// round 10
// speedup vs baseline: 1.3276x; 1.3276x over previous
#include <cuda_runtime.h>
#include <cuda_bf16.h>

#define Bn 64
#define Sn 1024
#define Vn 32000
#define Dn 1024
#define Hn 1024
#define En 1024
#define An 1024

// ---------------- scratch (no allocs allowed) ----------------
__device__ float g_q[Bn * An];
__device__ float g_score[Bn * Sn];
__device__ float g_xh0[Bn * 3072];   // [embedded(1024), context(1024), h0[0](1024)]
__device__ float g_xh1[Bn * 2048];   // [h1(1024), h0[1](1024)]
__device__ float g_gates[Bn * 4 * Hn];
__device__ float g_enc_tf[(size_t)Bn * Sn * En];  // tf32-rounded enc
__device__ float g_wae_tf[(size_t)An * En];       // tf32-rounded Wa_e

// ---------------- helpers ----------------
__device__ __forceinline__ unsigned f2tf(float f) {
    unsigned u;
    asm("cvt.rna.tf32.f32 %0, %1;" : "=r"(u) : "f"(f));
    return u;
}

__device__ __forceinline__ uint4 cvt4(float4 v) {
    uint4 o;
    o.x = f2tf(v.x); o.y = f2tf(v.y); o.z = f2tf(v.z); o.w = f2tf(v.w);
    return o;
}

__device__ __forceinline__ void mma_tf32(float* c, const unsigned* a, const unsigned* b) {
    asm volatile(
        "mma.sync.aligned.m16n8k8.row.col.f32.tf32.tf32.f32 "
        "{%0,%1,%2,%3}, {%4,%5,%6,%7}, {%8,%9}, {%0,%1,%2,%3};"
        : "+f"(c[0]), "+f"(c[1]), "+f"(c[2]), "+f"(c[3])
        : "r"(a[0]), "r"(a[1]), "r"(a[2]), "r"(a[3]), "r"(b[0]), "r"(b[1]));
}

__device__ __forceinline__ void ldsm4(unsigned* r, unsigned addr) {
    asm volatile("ldmatrix.sync.aligned.m8n8.x4.shared.b16 {%0,%1,%2,%3}, [%4];"
                 : "=r"(r[0]), "=r"(r[1]), "=r"(r[2]), "=r"(r[3]) : "r"(addr));
}

__device__ __forceinline__ void cp_async16(unsigned saddr, const void* gptr) {
    asm volatile("cp.async.ca.shared.global [%0], [%1], 16;" :: "r"(saddr), "l"(gptr));
}
__device__ __forceinline__ void cp_commit() { asm volatile("cp.async.commit_group;"); }

// ---------------- tf32 pre-convert ----------------
__global__ void tf32_convert(const float* __restrict__ src, float* __restrict__ dst) {
    size_t i = ((size_t)blockIdx.x * 256 + threadIdx.x) * 4;
    float4 v = *(const float4*)(src + i);
    *(uint4*)(dst + i) = cvt4(v);
}

// ---------------- embedding gather + h staging ----------------
__global__ void embed_kernel(const int* __restrict__ input_step,
                             const float* __restrict__ emb,
                             const float* __restrict__ h0,
                             float* __restrict__ xh0,
                             float* __restrict__ xh1) {
    int b = blockIdx.x;
    int row = input_step[b];
    const float* src = emb + (size_t)row * Dn;
    for (int d = threadIdx.x; d < Dn; d += blockDim.x) {
        xh0[(size_t)b * 3072 + d] = src[d];                    // embedded
        xh0[(size_t)b * 3072 + 2048 + d] = h0[b * Hn + d];     // h0[0]
        xh1[(size_t)b * 2048 + 1024 + d] = h0[Bn * Hn + b * Hn + d];  // h0[1]
    }
}

// ---------------- tf32 TC GEMM with split-K weights ----------------
// C[64,N] = A[64,Ktot] @ [W1 (N x K1); W2 (N x Ktot-K1)]^T + bias + bias2
// BM=64, BN=64, BK=32, 128 threads = 4 warps (2 m x 2 n), warp tile 32x32.
__global__ __launch_bounds__(128) void gemm_nt_tc2(
        const float* __restrict__ Amat, int Ktot,
        const float* __restrict__ W1, int K1, const float* __restrict__ W2,
        const float* __restrict__ bias, const float* __restrict__ bias2,
        float* __restrict__ Cmat, int N) {
    __shared__ char gsm[2][16384];  // per stage: A 8KB + W 8KB
    unsigned sbase = (unsigned)__cvta_generic_to_shared(gsm);

    int tid = threadIdx.x;
    int w = tid >> 5, lane = tid & 31, g = lane >> 2, tig = lane & 3;
    int n0 = blockIdx.x * 64;
    int mb = (w & 1) * 32;
    int nb = (w >> 1) * 32;
    int K2 = Ktot - K1;

    int lr = tid >> 3;       // 0..15
    int lc16 = tid & 7;      // 16B column

    int rA = mb + (lane & 15);
    int akh = (lane >> 4) & 1;
    unsigned aRow0 = rA * 128, aRow1 = (rA + 16) * 128;
    int am = rA & 7;
    int rB = nb + ((lane >> 1) & 8) + (lane & 7);
    int bkh = (lane >> 3) & 1;
    unsigned bRow0 = rB * 128, bRow1 = (rB + 16) * 128;
    int bm = rB & 7;

    float acc[2][4][4];
#pragma unroll
    for (int mt = 0; mt < 2; mt++)
#pragma unroll
        for (int nf = 0; nf < 4; nf++)
#pragma unroll
            for (int r = 0; r < 4; r++) acc[mt][nf][r] = 0.f;

#define WROW(row, k) ((k) < K1 ? W1 + (size_t)(row) * K1 + (k) \
                               : W2 + (size_t)(row) * K2 + ((k) - K1))

    float4 aReg[4], wReg[4];
#pragma unroll
    for (int i = 0; i < 4; i++) {
        int row = lr + 16 * i;
        aReg[i] = *(const float4*)&Amat[(size_t)row * Ktot + lc16 * 4];
        wReg[i] = *(const float4*)(WROW(n0 + row, 0) + lc16 * 4);
    }

    int st = 0;
    for (int k0 = 0; k0 < Ktot; k0 += 32) {
#pragma unroll
        for (int i = 0; i < 4; i++) {
            int row = lr + 16 * i;
            unsigned off = row * 128 + (unsigned)((lc16 ^ (row & 7)) << 4);
            *(uint4*)(gsm[st] + off) = cvt4(aReg[i]);
            *(uint4*)(gsm[st] + 8192 + off) = cvt4(wReg[i]);
        }
        __syncthreads();

        if (k0 + 32 < Ktot) {
#pragma unroll
            for (int i = 0; i < 4; i++) {
                int row = lr + 16 * i;
                aReg[i] = *(const float4*)&Amat[(size_t)row * Ktot + k0 + 32 + lc16 * 4];
                wReg[i] = *(const float4*)(WROW(n0 + row, k0 + 32) + lc16 * 4);
            }
        }

        unsigned Ab = sbase + st * 16384;
        unsigned Wb = Ab + 8192;
#pragma unroll
        for (int ks = 0; ks < 4; ks++) {
            unsigned a0[4], a1[4], b0[4], b1[4];
            unsigned acol = ((unsigned)(ks * 2 + akh) ^ am) << 4;
            unsigned bcol = ((unsigned)(ks * 2 + bkh) ^ bm) << 4;
            ldsm4(a0, Ab + aRow0 + acol);
            ldsm4(a1, Ab + aRow1 + acol);
            ldsm4(b0, Wb + bRow0 + bcol);
            ldsm4(b1, Wb + bRow1 + bcol);
            mma_tf32(acc[0][0], a0, b0);
            mma_tf32(acc[0][1], a0, b0 + 2);
            mma_tf32(acc[1][0], a1, b0);
            mma_tf32(acc[1][1], a1, b0 + 2);
            mma_tf32(acc[0][2], a0, b1);
            mma_tf32(acc[0][3], a0, b1 + 2);
            mma_tf32(acc[1][2], a1, b1);
            mma_tf32(acc[1][3], a1, b1 + 2);
        }
        __syncthreads();
        st ^= 1;
    }
#undef WROW

#pragma unroll
    for (int mt = 0; mt < 2; mt++) {
        int m0i = mb + mt * 16 + g;
        int m1i = m0i + 8;
#pragma unroll
        for (int nf = 0; nf < 4; nf++) {
            int n = n0 + nb + nf * 8 + 2 * tig;
            float badd0 = 0.f, badd1 = 0.f;
            if (bias)  { badd0 += bias[n];  badd1 += bias[n + 1]; }
            if (bias2) { badd0 += bias2[n]; badd1 += bias2[n + 1]; }
            Cmat[(size_t)m0i * N + n]     = acc[mt][nf][0] + badd0;
            Cmat[(size_t)m0i * N + n + 1] = acc[mt][nf][1] + badd1;
            Cmat[(size_t)m1i * N + n]     = acc[mt][nf][2] + badd0;
            Cmat[(size_t)m1i * N + n + 1] = acc[mt][nf][3] + badd1;
        }
    }
}

// ---------------- score init ----------------
__global__ void score_init_kernel(const float* __restrict__ bva, float* __restrict__ score) {
    int i = blockIdx.x * blockDim.x + threadIdx.x;
    if (i < Bn * Sn) score[i] = bva[0];
}

// ---------------- fused attention score GEMM (r7 winner) ----------------
// BM=128, BN=128, BK=32, 512 threads (16 warps: 4m x 4n, warp tile 32x32).
// 3-stage cp.async pipeline, pre-converted tf32 inputs.
// grid: (A/128 = 8, BS/128 = 512), x fastest -> enc tile L2 reuse.
__global__ __launch_bounds__(512) void score_gemm_mma(
        const float* __restrict__ enc_tf, const float* __restrict__ wae_tf,
        const float* __restrict__ ba_e, const float* __restrict__ q,
        const float* __restrict__ va, float* __restrict__ score) {
    extern __shared__ char smem_raw[];
    unsigned sbase = (unsigned)__cvta_generic_to_shared(smem_raw);
    const unsigned STAGE = 32768;  // A 16KB + W 16KB
    float* qb  = (float*)(smem_raw + 3 * STAGE);
    float* vas = qb + 128;

    int tid = threadIdx.x;
    int w = tid >> 5, lane = tid & 31, g = lane >> 2, tig = lane & 3;
    int n0 = blockIdx.x * 128;
    int m0 = blockIdx.y * 128;
    int b = m0 >> 10;
    int mb = (w >> 2) * 32;
    int nb = (w & 3) * 32;

    if (tid < 128) {
        qb[tid]  = q[b * An + n0 + tid] + ba_e[n0 + tid];
        vas[tid] = va[n0 + tid];
    }

    int crow = tid >> 3;    // 0..63
    int ccol = tid & 7;
    const float* encp = enc_tf + (size_t)m0 * En;
    const float* waep = wae_tf + (size_t)n0 * En;

    int rA = mb + (lane & 15);
    int akh = (lane >> 4) & 1;
    unsigned aRow0 = rA * 128, aRow1 = (rA + 16) * 128;
    int am = rA & 7;
    int rB = nb + ((lane >> 1) & 8) + (lane & 7);
    int bkh = (lane >> 3) & 1;
    unsigned bRow0 = rB * 128, bRow1 = (rB + 16) * 128;
    int bm = rB & 7;

    float acc[2][4][4];
#pragma unroll
    for (int mt = 0; mt < 2; mt++)
#pragma unroll
        for (int nf = 0; nf < 4; nf++)
#pragma unroll
            for (int r = 0; r < 4; r++) acc[mt][nf][r] = 0.f;

#define PREFETCH(st, k0)                                                          \
    do {                                                                          \
        unsigned Ad = sbase + (st) * STAGE;                                       \
        unsigned Wd = Ad + 16384;                                                 \
        _Pragma("unroll")                                                         \
        for (int i = 0; i < 2; i++) {                                             \
            int row = crow + i * 64;                                              \
            cp_async16(Ad + row * 128 + ((ccol ^ (row & 7)) << 4),                \
                       encp + (size_t)row * En + (k0) + ccol * 4);                \
        }                                                                         \
        _Pragma("unroll")                                                         \
        for (int i = 0; i < 2; i++) {                                             \
            int row = crow + i * 64;                                              \
            cp_async16(Wd + row * 128 + ((ccol ^ (row & 7)) << 4),                \
                       waep + (size_t)row * En + (k0) + ccol * 4);                \
        }                                                                         \
        cp_commit();                                                              \
    } while (0)

    PREFETCH(0, 0);
    PREFETCH(1, 32);

    const int NT = En / 32;
    int st = 0;
    for (int it = 0; it < NT; it++) {
        if (it == NT - 1) asm volatile("cp.async.wait_group 0;");
        else              asm volatile("cp.async.wait_group 1;");
        __syncthreads();

        unsigned Ab = sbase + st * STAGE;
        unsigned Wb = Ab + 16384;
#pragma unroll
        for (int ks = 0; ks < 4; ks++) {
            unsigned a0[4], a1[4], b0[4], b1[4];
            unsigned acol = ((unsigned)(ks * 2 + akh) ^ am) << 4;
            unsigned bcol = ((unsigned)(ks * 2 + bkh) ^ bm) << 4;
            ldsm4(a0, Ab + aRow0 + acol);
            ldsm4(a1, Ab + aRow1 + acol);
            ldsm4(b0, Wb + bRow0 + bcol);
            ldsm4(b1, Wb + bRow1 + bcol);
            mma_tf32(acc[0][0], a0, b0);
            mma_tf32(acc[0][1], a0, b0 + 2);
            mma_tf32(acc[1][0], a1, b0);
            mma_tf32(acc[1][1], a1, b0 + 2);
            mma_tf32(acc[0][2], a0, b1);
            mma_tf32(acc[0][3], a0, b1 + 2);
            mma_tf32(acc[1][2], a1, b1);
            mma_tf32(acc[1][3], a1, b1 + 2);
        }

        int pf = it + 2;
        if (pf < NT) PREFETCH(pf % 3, pf * 32);
        st = (st + 1 == 3) ? 0 : st + 1;
    }
#undef PREFETCH

    // epilogue: tanh + va-weighted row reduction
#pragma unroll
    for (int mt = 0; mt < 2; mt++) {
        float sumlo = 0.f, sumhi = 0.f;
#pragma unroll
        for (int nf = 0; nf < 4; nf++) {
            int nl = nb + nf * 8 + 2 * tig;
            float q0 = qb[nl], q1 = qb[nl + 1];
            float v0 = vas[nl], v1 = vas[nl + 1];
            sumlo += v0 * tanhf(acc[mt][nf][0] + q0) + v1 * tanhf(acc[mt][nf][1] + q1);
            sumhi += v0 * tanhf(acc[mt][nf][2] + q0) + v1 * tanhf(acc[mt][nf][3] + q1);
        }
        sumlo += __shfl_xor_sync(0xffffffffu, sumlo, 1);
        sumlo += __shfl_xor_sync(0xffffffffu, sumlo, 2);
        sumhi += __shfl_xor_sync(0xffffffffu, sumhi, 1);
        sumhi += __shfl_xor_sync(0xffffffffu, sumhi, 2);
        if (tig == 0) {
            int r = m0 + mb + mt * 16 + g;
            atomicAdd(&score[r], sumlo);
            atomicAdd(&score[r + 8], sumhi);
        }
    }
}

// ---------------- softmax ----------------
__global__ void softmax_kernel(const float* __restrict__ score, float* __restrict__ attn) {
    __shared__ float sh[Sn];
    __shared__ float red[256];
    int b = blockIdx.x;
    int tid = threadIdx.x;

    float lmax = -3.4e38f;
    for (int s = tid; s < Sn; s += 256) {
        float v = score[b * Sn + s];
        sh[s] = v;
        lmax = fmaxf(lmax, v);
    }
    red[tid] = lmax;
    __syncthreads();
    for (int off = 128; off > 0; off >>= 1) {
        if (tid < off) red[tid] = fmaxf(red[tid], red[tid + off]);
        __syncthreads();
    }
    float m = red[0];
    __syncthreads();

    float lsum = 0.f;
    for (int s = tid; s < Sn; s += 256) {
        float e = expf(sh[s] - m);
        sh[s] = e;
        lsum += e;
    }
    red[tid] = lsum;
    __syncthreads();
    for (int off = 128; off > 0; off >>= 1) {
        if (tid < off) red[tid] += red[tid + off];
        __syncthreads();
    }
    float inv = 1.f / red[0];
    __syncthreads();

    for (int s = tid; s < Sn; s += 256) attn[b * Sn + s] = sh[s] * inv;
}

// ---------------- context = attn @ enc (writes into xh0 middle slot) ----------------
__global__ void context_kernel(const float* __restrict__ enc,
                               const float* __restrict__ attn,
                               float* __restrict__ xh0) {
    __shared__ float w[Sn];
    int b = blockIdx.x;
    int e = blockIdx.y * 256 + threadIdx.x;
    for (int s = threadIdx.x; s < Sn; s += 256) w[s] = attn[b * Sn + s];
    __syncthreads();
    const float* ep = enc + (size_t)b * Sn * En + e;
    float acc = 0.f;
#pragma unroll 8
    for (int s = 0; s < Sn; s++) acc += w[s] * ep[(size_t)s * En];
    xh0[(size_t)b * 3072 + 1024 + e] = acc;
}

// ---------------- LSTM pointwise (optionally stages h into concat buffer) ----------------
__global__ void lstm_pointwise(const float* __restrict__ gates,
                               const float* __restrict__ cprev,
                               float* __restrict__ hout,
                               float* __restrict__ cout,
                               float* __restrict__ hcopy, int hstride) {
    int idx = blockIdx.x * 256 + threadIdx.x;
    if (idx >= Bn * Hn) return;
    int b = idx >> 10;
    int h = idx & 1023;
    const float* g = gates + (size_t)b * 4 * Hn;
    float ig = 1.f / (1.f + expf(-g[h]));
    float fg = 1.f / (1.f + expf(-g[Hn + h]));
    float gg = tanhf(g[2 * Hn + h]);
    float og = 1.f / (1.f + expf(-g[3 * Hn + h]));
    float c = fg * cprev[idx] + ig * gg;
    float hv = og * tanhf(c);
    hout[idx] = hv;
    cout[idx] = c;
    if (hcopy) hcopy[(size_t)b * hstride + h] = hv;
}

// ---------------- launcher ----------------
extern "C" void kernel_launch(void* const* d_in, const int* in_sizes, int n_in,
                              void* d_out, int out_size) {
    const int*   input_step = (const int*)d_in[0];
    const float* h0    = (const float*)d_in[1];
    const float* c0    = (const float*)d_in[2];
    const float* enc   = (const float*)d_in[3];
    const float* emb   = (const float*)d_in[4];
    const float* Wa_h  = (const float*)d_in[5];
    const float* ba_h  = (const float*)d_in[6];
    const float* Wa_e  = (const float*)d_in[7];
    const float* ba_e  = (const float*)d_in[8];
    const float* va    = (const float*)d_in[9];
    const float* bva   = (const float*)d_in[10];
    const float* Wih0  = (const float*)d_in[11];
    const float* Whh0  = (const float*)d_in[12];
    const float* bih0  = (const float*)d_in[13];
    const float* bhh0  = (const float*)d_in[14];
    const float* Wih1  = (const float*)d_in[15];
    const float* Whh1  = (const float*)d_in[16];
    const float* bih1  = (const float*)d_in[17];
    const float* bhh1  = (const float*)d_in[18];
    const float* Wout  = (const float*)d_in[19];
    const float* bout  = (const float*)d_in[20];

    float* out = (float*)d_out;
    float* out_logits = out;
    float* out_h      = out_logits + Bn * Vn;
    float* out_c      = out_h + 2 * Bn * Hn;
    float* out_attn   = out_c + 2 * Bn * Hn;

    float* q_buf;     cudaGetSymbolAddress((void**)&q_buf, g_q);
    float* score_buf; cudaGetSymbolAddress((void**)&score_buf, g_score);
    float* xh0;       cudaGetSymbolAddress((void**)&xh0, g_xh0);
    float* xh1;       cudaGetSymbolAddress((void**)&xh1, g_xh1);
    float* gates_buf; cudaGetSymbolAddress((void**)&gates_buf, g_gates);
    float* enc_tf;    cudaGetSymbolAddress((void**)&enc_tf, g_enc_tf);
    float* wae_tf;    cudaGetSymbolAddress((void**)&wae_tf, g_wae_tf);

    const int score_smem = 3 * 32768 + 1024;  // 99328
    cudaFuncSetAttribute(score_gemm_mma, cudaFuncAttributeMaxDynamicSharedMemorySize,
                         score_smem);

    // 0. pre-round enc and Wa_e to tf32 (rna)
    tf32_convert<<<(Bn * Sn * En) / 1024, 256>>>(enc, enc_tf);
    tf32_convert<<<(An * En) / 1024, 256>>>(Wa_e, wae_tf);

    // 1. embedding gather + h0 staging
    embed_kernel<<<Bn, 256>>>(input_step, emb, h0, xh0, xh1);

    // 2. q = h0[1] @ Wa_h^T + ba_h
    gemm_nt_tc2<<<An / 64, 128>>>(h0 + Bn * Hn, Hn, Wa_h, Hn, nullptr,
                                  ba_h, nullptr, q_buf, An);

    // 3. fused tf32 score GEMM
    score_init_kernel<<<(Bn * Sn + 255) / 256, 256>>>(bva, score_buf);
    {
        dim3 grid(An / 128, Bn * Sn / 128);
        score_gemm_mma<<<grid, 512, score_smem>>>(enc_tf, wae_tf, ba_e, q_buf, va, score_buf);
    }

    // 4. softmax
    softmax_kernel<<<Bn, 256>>>(score_buf, out_attn);

    // 5. context -> xh0[:, 1024:2048]
    {
        dim3 grid(Bn, En / 256);
        context_kernel<<<grid, 256>>>(enc, out_attn, xh0);
    }

    // 6. LSTM layer 0: gates = [x, h0[0]] @ [Wih0; Whh0]^T + biases
    gemm_nt_tc2<<<4 * Hn / 64, 128>>>(xh0, 3072, Wih0, Dn + En, Whh0,
                                      bih0, bhh0, gates_buf, 4 * Hn);
    lstm_pointwise<<<(Bn * Hn + 255) / 256, 256>>>(gates_buf, c0, out_h, out_c,
                                                   xh1, 2048);

    // 7. LSTM layer 1: gates = [h1, h0[1]] @ [Wih1; Whh1]^T + biases
    gemm_nt_tc2<<<4 * Hn / 64, 128>>>(xh1, 2048, Wih1, Hn, Whh1,
                                      bih1, bhh1, gates_buf, 4 * Hn);
    lstm_pointwise<<<(Bn * Hn + 255) / 256, 256>>>(gates_buf, c0 + Bn * Hn,
                                                   out_h + Bn * Hn, out_c + Bn * Hn,
                                                   nullptr, 0);

    // 8. logits = h2 @ Wout^T + bout
    gemm_nt_tc2<<<Vn / 64, 128>>>(out_h + Bn * Hn, Hn, Wout, Hn, nullptr,
                                  bout, nullptr, out_logits, Vn);
}

// round 12
// speedup vs baseline: 1.3742x; 1.0351x over previous
#include <cuda_runtime.h>
#include <cuda_bf16.h>

#define Bn 64
#define Sn 1024
#define Vn 32000
#define Dn 1024
#define Hn 1024
#define En 1024
#define An 1024

// ---------------- scratch (no allocs allowed) ----------------
__device__ float g_q[Bn * An];
__device__ float g_score[Bn * Sn];
__device__ float g_xh0[Bn * 3072];   // [embedded(1024), context(1024), h0[0](1024)]
__device__ float g_xh1[Bn * 2048];   // [h1(1024), h0[1](1024)]
__device__ float g_gates[Bn * 4 * Hn];

// ---------------- helpers ----------------
__device__ __forceinline__ unsigned f2tf(float f) {
    unsigned u;
    asm("cvt.rna.tf32.f32 %0, %1;" : "=r"(u) : "f"(f));
    return u;
}

__device__ __forceinline__ uint4 cvt4(float4 v) {
    uint4 o;
    o.x = f2tf(v.x); o.y = f2tf(v.y); o.z = f2tf(v.z); o.w = f2tf(v.w);
    return o;
}

__device__ __forceinline__ void mma_tf32(float* c, const unsigned* a, const unsigned* b) {
    asm volatile(
        "mma.sync.aligned.m16n8k8.row.col.f32.tf32.tf32.f32 "
        "{%0,%1,%2,%3}, {%4,%5,%6,%7}, {%8,%9}, {%0,%1,%2,%3};"
        : "+f"(c[0]), "+f"(c[1]), "+f"(c[2]), "+f"(c[3])
        : "r"(a[0]), "r"(a[1]), "r"(a[2]), "r"(a[3]), "r"(b[0]), "r"(b[1]));
}

__device__ __forceinline__ void ldsm4(unsigned* r, unsigned addr) {
    asm volatile("ldmatrix.sync.aligned.m8n8.x4.shared.b16 {%0,%1,%2,%3}, [%4];"
                 : "=r"(r[0]), "=r"(r[1]), "=r"(r[2]), "=r"(r[3]) : "r"(addr));
}

__device__ __forceinline__ void cp_async16(unsigned saddr, const void* gptr) {
    asm volatile("cp.async.ca.shared.global [%0], [%1], 16;" :: "r"(saddr), "l"(gptr));
}
__device__ __forceinline__ void cp_commit() { asm volatile("cp.async.commit_group;"); }

__device__ __forceinline__ unsigned smem_u32(const void* p) {
    unsigned a;
    asm("{ .reg .u64 t; cvta.to.shared.u64 t, %1; cvt.u32.u64 %0, t; }" : "=r"(a) : "l"(p));
    return a;
}

// ---------------- embedding gather + h staging ----------------
__global__ void embed_kernel(const int* __restrict__ input_step,
                             const float* __restrict__ emb,
                             const float* __restrict__ h0,
                             float* __restrict__ xh0,
                             float* __restrict__ xh1) {
    int b = blockIdx.x;
    int row = input_step[b];
    const float* src = emb + (size_t)row * Dn;
    for (int d = threadIdx.x; d < Dn; d += blockDim.x) {
        xh0[(size_t)b * 3072 + d] = src[d];
        xh0[(size_t)b * 3072 + 2048 + d] = h0[b * Hn + d];
        xh1[(size_t)b * 2048 + 1024 + d] = h0[Bn * Hn + b * Hn + d];
    }
}

// ---------------- tf32 TC GEMM with split-K weights (warp mma; small GEMMs) ----------------
// C[64,N] = A[64,Ktot] @ [W1 (N x K1); W2 (N x Ktot-K1)]^T + bias + bias2
// BM=64, BN=64, BK=32, 128 threads = 4 warps (2 m x 2 n), warp tile 32x32.
__global__ __launch_bounds__(128) void gemm_nt_tc2(
        const float* __restrict__ Amat, int Ktot,
        const float* __restrict__ W1, int K1, const float* __restrict__ W2,
        const float* __restrict__ bias, const float* __restrict__ bias2,
        float* __restrict__ Cmat, int N) {
    __shared__ char gsm[2][16384];
    unsigned sbase = smem_u32(gsm);

    int tid = threadIdx.x;
    int w = tid >> 5, lane = tid & 31, g = lane >> 2, tig = lane & 3;
    int n0 = blockIdx.x * 64;
    int mb = (w & 1) * 32;
    int nb = (w >> 1) * 32;
    int K2 = Ktot - K1;

    int lr = tid >> 3;
    int lc16 = tid & 7;

    int rA = mb + (lane & 15);
    int akh = (lane >> 4) & 1;
    unsigned aRow0 = rA * 128, aRow1 = (rA + 16) * 128;
    int am = rA & 7;
    int rB = nb + ((lane >> 1) & 8) + (lane & 7);
    int bkh = (lane >> 3) & 1;
    unsigned bRow0 = rB * 128, bRow1 = (rB + 16) * 128;
    int bm = rB & 7;

    float acc[2][4][4];
#pragma unroll
    for (int mt = 0; mt < 2; mt++)
#pragma unroll
        for (int nf = 0; nf < 4; nf++)
#pragma unroll
            for (int r = 0; r < 4; r++) acc[mt][nf][r] = 0.f;

#define WROW(row, k) ((k) < K1 ? W1 + (size_t)(row) * K1 + (k) \
                               : W2 + (size_t)(row) * K2 + ((k) - K1))

    float4 aReg[4], wReg[4];
#pragma unroll
    for (int i = 0; i < 4; i++) {
        int row = lr + 16 * i;
        aReg[i] = *(const float4*)&Amat[(size_t)row * Ktot + lc16 * 4];
        wReg[i] = *(const float4*)(WROW(n0 + row, 0) + lc16 * 4);
    }

    int st = 0;
    for (int k0 = 0; k0 < Ktot; k0 += 32) {
#pragma unroll
        for (int i = 0; i < 4; i++) {
            int row = lr + 16 * i;
            unsigned off = row * 128 + (unsigned)((lc16 ^ (row & 7)) << 4);
            *(uint4*)(gsm[st] + off) = cvt4(aReg[i]);
            *(uint4*)(gsm[st] + 8192 + off) = cvt4(wReg[i]);
        }
        __syncthreads();

        if (k0 + 32 < Ktot) {
#pragma unroll
            for (int i = 0; i < 4; i++) {
                int row = lr + 16 * i;
                aReg[i] = *(const float4*)&Amat[(size_t)row * Ktot + k0 + 32 + lc16 * 4];
                wReg[i] = *(const float4*)(WROW(n0 + row, k0 + 32) + lc16 * 4);
            }
        }

        unsigned Ab = sbase + st * 16384;
        unsigned Wb = Ab + 8192;
#pragma unroll
        for (int ks = 0; ks < 4; ks++) {
            unsigned a0[4], a1[4], b0[4], b1[4];
            unsigned acol = ((unsigned)(ks * 2 + akh) ^ am) << 4;
            unsigned bcol = ((unsigned)(ks * 2 + bkh) ^ bm) << 4;
            ldsm4(a0, Ab + aRow0 + acol);
            ldsm4(a1, Ab + aRow1 + acol);
            ldsm4(b0, Wb + bRow0 + bcol);
            ldsm4(b1, Wb + bRow1 + bcol);
            mma_tf32(acc[0][0], a0, b0);
            mma_tf32(acc[0][1], a0, b0 + 2);
            mma_tf32(acc[1][0], a1, b0);
            mma_tf32(acc[1][1], a1, b0 + 2);
            mma_tf32(acc[0][2], a0, b1);
            mma_tf32(acc[0][3], a0, b1 + 2);
            mma_tf32(acc[1][2], a1, b1);
            mma_tf32(acc[1][3], a1, b1 + 2);
        }
        __syncthreads();
        st ^= 1;
    }
#undef WROW

#pragma unroll
    for (int mt = 0; mt < 2; mt++) {
        int m0i = mb + mt * 16 + g;
        int m1i = m0i + 8;
#pragma unroll
        for (int nf = 0; nf < 4; nf++) {
            int n = n0 + nb + nf * 8 + 2 * tig;
            float badd0 = 0.f, badd1 = 0.f;
            if (bias)  { badd0 += bias[n];  badd1 += bias[n + 1]; }
            if (bias2) { badd0 += bias2[n]; badd1 += bias2[n + 1]; }
            Cmat[(size_t)m0i * N + n]     = acc[mt][nf][0] + badd0;
            Cmat[(size_t)m0i * N + n + 1] = acc[mt][nf][1] + badd1;
            Cmat[(size_t)m1i * N + n]     = acc[mt][nf][2] + badd0;
            Cmat[(size_t)m1i * N + n + 1] = acc[mt][nf][3] + badd1;
        }
    }
}

// ---------------- score init ----------------
__global__ void score_init_kernel(const float* __restrict__ bva, float* __restrict__ score) {
    int i = blockIdx.x * blockDim.x + threadIdx.x;
    if (i < Bn * Sn) score[i] = bva[0];
}

// ---------------- fused attention score GEMM (r7 structure, raw fp32 inputs) ----------------
// BM=128, BN=128, BK=32, 512 threads (16 warps: 4m x 4n, warp tile 32x32).
// 3-stage cp.async pipeline. Inputs are RAW fp32: tf32 MMA truncates low mantissa
// bits in hardware (no pre-convert pass needed).
// grid: (A/128 = 8, BS/128 = 512), x fastest -> enc tile L2 reuse.
__global__ __launch_bounds__(512) void score_gemm_mma(
        const float* __restrict__ enc, const float* __restrict__ wae,
        const float* __restrict__ ba_e, const float* __restrict__ q,
        const float* __restrict__ va, float* __restrict__ score) {
    extern __shared__ char smem_raw[];
    unsigned sbase = smem_u32(smem_raw);
    const unsigned STAGE = 32768;  // A 16KB + W 16KB
    float* qb  = (float*)(smem_raw + 3 * STAGE);
    float* vas = qb + 128;

    int tid = threadIdx.x;
    int w = tid >> 5, lane = tid & 31, g = lane >> 2, tig = lane & 3;
    int n0 = blockIdx.x * 128;
    int m0 = blockIdx.y * 128;
    int b = m0 >> 10;
    int mb = (w >> 2) * 32;
    int nb = (w & 3) * 32;

    if (tid < 128) {
        qb[tid]  = q[b * An + n0 + tid] + ba_e[n0 + tid];
        vas[tid] = va[n0 + tid];
    }

    int crow = tid >> 3;    // 0..63
    int ccol = tid & 7;
    const float* encp = enc + (size_t)m0 * En;
    const float* waep = wae + (size_t)n0 * En;

    int rA = mb + (lane & 15);
    int akh = (lane >> 4) & 1;
    unsigned aRow0 = rA * 128, aRow1 = (rA + 16) * 128;
    int am = rA & 7;
    int rB = nb + ((lane >> 1) & 8) + (lane & 7);
    int bkh = (lane >> 3) & 1;
    unsigned bRow0 = rB * 128, bRow1 = (rB + 16) * 128;
    int bm = rB & 7;

    float acc[2][4][4];
#pragma unroll
    for (int mt = 0; mt < 2; mt++)
#pragma unroll
        for (int nf = 0; nf < 4; nf++)
#pragma unroll
            for (int r = 0; r < 4; r++) acc[mt][nf][r] = 0.f;

#define PREFETCH(st, k0)                                                          \
    do {                                                                          \
        unsigned Ad = sbase + (st) * STAGE;                                       \
        unsigned Wd = Ad + 16384;                                                 \
        _Pragma("unroll")                                                         \
        for (int i = 0; i < 2; i++) {                                             \
            int row = crow + i * 64;                                              \
            cp_async16(Ad + row * 128 + ((ccol ^ (row & 7)) << 4),                \
                       encp + (size_t)row * En + (k0) + ccol * 4);                \
        }                                                                         \
        _Pragma("unroll")                                                         \
        for (int i = 0; i < 2; i++) {                                             \
            int row = crow + i * 64;                                              \
            cp_async16(Wd + row * 128 + ((ccol ^ (row & 7)) << 4),                \
                       waep + (size_t)row * En + (k0) + ccol * 4);                \
        }                                                                         \
        cp_commit();                                                              \
    } while (0)

    PREFETCH(0, 0);
    PREFETCH(1, 32);

    const int NT = En / 32;
    int st = 0;
    for (int it = 0; it < NT; it++) {
        if (it == NT - 1) asm volatile("cp.async.wait_group 0;");
        else              asm volatile("cp.async.wait_group 1;");
        __syncthreads();

        unsigned Ab = sbase + st * STAGE;
        unsigned Wb = Ab + 16384;
#pragma unroll
        for (int ks = 0; ks < 4; ks++) {
            unsigned a0[4], a1[4], b0[4], b1[4];
            unsigned acol = ((unsigned)(ks * 2 + akh) ^ am) << 4;
            unsigned bcol = ((unsigned)(ks * 2 + bkh) ^ bm) << 4;
            ldsm4(a0, Ab + aRow0 + acol);
            ldsm4(a1, Ab + aRow1 + acol);
            ldsm4(b0, Wb + bRow0 + bcol);
            ldsm4(b1, Wb + bRow1 + bcol);
            mma_tf32(acc[0][0], a0, b0);
            mma_tf32(acc[0][1], a0, b0 + 2);
            mma_tf32(acc[1][0], a1, b0);
            mma_tf32(acc[1][1], a1, b0 + 2);
            mma_tf32(acc[0][2], a0, b1);
            mma_tf32(acc[0][3], a0, b1 + 2);
            mma_tf32(acc[1][2], a1, b1);
            mma_tf32(acc[1][3], a1, b1 + 2);
        }

        int pf = it + 2;
        if (pf < NT) PREFETCH(pf % 3, pf * 32);
        st = (st + 1 == 3) ? 0 : st + 1;
    }
#undef PREFETCH

    // epilogue: tanh + va-weighted row reduction
#pragma unroll
    for (int mt = 0; mt < 2; mt++) {
        float sumlo = 0.f, sumhi = 0.f;
#pragma unroll
        for (int nf = 0; nf < 4; nf++) {
            int nl = nb + nf * 8 + 2 * tig;
            float q0 = qb[nl], q1 = qb[nl + 1];
            float v0 = vas[nl], v1 = vas[nl + 1];
            sumlo += v0 * tanhf(acc[mt][nf][0] + q0) + v1 * tanhf(acc[mt][nf][1] + q1);
            sumhi += v0 * tanhf(acc[mt][nf][2] + q0) + v1 * tanhf(acc[mt][nf][3] + q1);
        }
        sumlo += __shfl_xor_sync(0xffffffffu, sumlo, 1);
        sumlo += __shfl_xor_sync(0xffffffffu, sumlo, 2);
        sumhi += __shfl_xor_sync(0xffffffffu, sumhi, 1);
        sumhi += __shfl_xor_sync(0xffffffffu, sumhi, 2);
        if (tig == 0) {
            int r = m0 + mb + mt * 16 + g;
            atomicAdd(&score[r], sumlo);
            atomicAdd(&score[r + 8], sumhi);
        }
    }
}

// ---------------- softmax ----------------
__global__ void softmax_kernel(const float* __restrict__ score, float* __restrict__ attn) {
    __shared__ float sh[Sn];
    __shared__ float red[256];
    int b = blockIdx.x;
    int tid = threadIdx.x;

    float lmax = -3.4e38f;
    for (int s = tid; s < Sn; s += 256) {
        float v = score[b * Sn + s];
        sh[s] = v;
        lmax = fmaxf(lmax, v);
    }
    red[tid] = lmax;
    __syncthreads();
    for (int off = 128; off > 0; off >>= 1) {
        if (tid < off) red[tid] = fmaxf(red[tid], red[tid + off]);
        __syncthreads();
    }
    float m = red[0];
    __syncthreads();

    float lsum = 0.f;
    for (int s = tid; s < Sn; s += 256) {
        float e = expf(sh[s] - m);
        sh[s] = e;
        lsum += e;
    }
    red[tid] = lsum;
    __syncthreads();
    for (int off = 128; off > 0; off >>= 1) {
        if (tid < off) red[tid] += red[tid + off];
        __syncthreads();
    }
    float inv = 1.f / red[0];
    __syncthreads();

    for (int s = tid; s < Sn; s += 256) attn[b * Sn + s] = sh[s] * inv;
}

// ---------------- context = attn @ enc (writes into xh0 middle slot) ----------------
__global__ void context_kernel(const float* __restrict__ enc,
                               const float* __restrict__ attn,
                               float* __restrict__ xh0) {
    __shared__ float w[Sn];
    int b = blockIdx.x;
    int e = blockIdx.y * 256 + threadIdx.x;
    for (int s = threadIdx.x; s < Sn; s += 256) w[s] = attn[b * Sn + s];
    __syncthreads();
    const float* ep = enc + (size_t)b * Sn * En + e;
    float acc = 0.f;
#pragma unroll 8
    for (int s = 0; s < Sn; s++) acc += w[s] * ep[(size_t)s * En];
    xh0[(size_t)b * 3072 + 1024 + e] = acc;
}

// ---------------- LSTM pointwise ----------------
__global__ void lstm_pointwise(const float* __restrict__ gates,
                               const float* __restrict__ cprev,
                               float* __restrict__ hout,
                               float* __restrict__ cout,
                               float* __restrict__ hcopy, int hstride) {
    int idx = blockIdx.x * 256 + threadIdx.x;
    if (idx >= Bn * Hn) return;
    int b = idx >> 10;
    int h = idx & 1023;
    const float* g = gates + (size_t)b * 4 * Hn;
    float ig = 1.f / (1.f + expf(-g[h]));
    float fg = 1.f / (1.f + expf(-g[Hn + h]));
    float gg = tanhf(g[2 * Hn + h]);
    float og = 1.f / (1.f + expf(-g[3 * Hn + h]));
    float c = fg * cprev[idx] + ig * gg;
    float hv = og * tanhf(c);
    hout[idx] = hv;
    cout[idx] = c;
    if (hcopy) hcopy[(size_t)b * hstride + h] = hv;
}

// ---------------- launcher ----------------
extern "C" void kernel_launch(void* const* d_in, const int* in_sizes, int n_in,
                              void* d_out, int out_size) {
    const int*   input_step = (const int*)d_in[0];
    const float* h0    = (const float*)d_in[1];
    const float* c0    = (const float*)d_in[2];
    const float* enc   = (const float*)d_in[3];
    const float* emb   = (const float*)d_in[4];
    const float* Wa_h  = (const float*)d_in[5];
    const float* ba_h  = (const float*)d_in[6];
    const float* Wa_e  = (const float*)d_in[7];
    const float* ba_e  = (const float*)d_in[8];
    const float* va    = (const float*)d_in[9];
    const float* bva   = (const float*)d_in[10];
    const float* Wih0  = (const float*)d_in[11];
    const float* Whh0  = (const float*)d_in[12];
    const float* bih0  = (const float*)d_in[13];
    const float* bhh0  = (const float*)d_in[14];
    const float* Wih1  = (const float*)d_in[15];
    const float* Whh1  = (const float*)d_in[16];
    const float* bih1  = (const float*)d_in[17];
    const float* bhh1  = (const float*)d_in[18];
    const float* Wout  = (const float*)d_in[19];
    const float* bout  = (const float*)d_in[20];

    float* out = (float*)d_out;
    float* out_logits = out;
    float* out_h      = out_logits + Bn * Vn;
    float* out_c      = out_h + 2 * Bn * Hn;
    float* out_attn   = out_c + 2 * Bn * Hn;

    float* q_buf;     cudaGetSymbolAddress((void**)&q_buf, g_q);
    float* score_buf; cudaGetSymbolAddress((void**)&score_buf, g_score);
    float* xh0;       cudaGetSymbolAddress((void**)&xh0, g_xh0);
    float* xh1;       cudaGetSymbolAddress((void**)&xh1, g_xh1);
    float* gates_buf; cudaGetSymbolAddress((void**)&gates_buf, g_gates);

    const int score_smem = 3 * 32768 + 1024;  // 99328
    cudaFuncSetAttribute(score_gemm_mma, cudaFuncAttributeMaxDynamicSharedMemorySize,
                         score_smem);

    // 1. embedding gather + h0 staging
    embed_kernel<<<Bn, 256>>>(input_step, emb, h0, xh0, xh1);

    // 2. q = h0[1] @ Wa_h^T + ba_h
    gemm_nt_tc2<<<An / 64, 128>>>(h0 + Bn * Hn, Hn, Wa_h, Hn, nullptr,
                                  ba_h, nullptr, q_buf, An);

    // 3. fused tf32 score GEMM (raw fp32 inputs; HW truncation rounding)
    score_init_kernel<<<(Bn * Sn + 255) / 256, 256>>>(bva, score_buf);
    {
        dim3 grid(An / 128, Bn * Sn / 128);
        score_gemm_mma<<<grid, 512, score_smem>>>(enc, Wa_e, ba_e, q_buf, va, score_buf);
    }

    // 4. softmax
    softmax_kernel<<<Bn, 256>>>(score_buf, out_attn);

    // 5. context -> xh0[:, 1024:2048]
    {
        dim3 grid(Bn, En / 256);
        context_kernel<<<grid, 256>>>(enc, out_attn, xh0);
    }

    // 6. LSTM layer 0: gates = [x, h0[0]] @ [Wih0; Whh0]^T + biases
    gemm_nt_tc2<<<4 * Hn / 64, 128>>>(xh0, 3072, Wih0, Dn + En, Whh0,
                                      bih0, bhh0, gates_buf, 4 * Hn);
    lstm_pointwise<<<(Bn * Hn + 255) / 256, 256>>>(gates_buf, c0, out_h, out_c,
                                                   xh1, 2048);

    // 7. LSTM layer 1: gates = [h1, h0[1]] @ [Wih1; Whh1]^T + biases
    gemm_nt_tc2<<<4 * Hn / 64, 128>>>(xh1, 2048, Wih1, Hn, Whh1,
                                      bih1, bhh1, gates_buf, 4 * Hn);
    lstm_pointwise<<<(Bn * Hn + 255) / 256, 256>>>(gates_buf, c0 + Bn * Hn,
                                                   out_h + Bn * Hn, out_c + Bn * Hn,
                                                   nullptr, 0);

    // 8. logits = h2 @ Wout^T + bout
    gemm_nt_tc2<<<Vn / 64, 128>>>(out_h + Bn * Hn, Hn, Wout, Hn, nullptr,
                                  bout, nullptr, out_logits, Vn);
}

// round 13
// speedup vs baseline: 1.8925x; 1.3771x over previous
#include <cuda_runtime.h>
#include <cuda_bf16.h>
#include <cuda_fp16.h>

#define Bn 64
#define Sn 1024
#define Vn 32000
#define Dn 1024
#define Hn 1024
#define En 1024
#define An 1024

// ---------------- scratch (no allocs allowed) ----------------
__device__ float g_q[Bn * An];
__device__ float g_score[Bn * Sn];
__device__ float g_xh0[Bn * 3072];   // [embedded(1024), context(1024), h0[0](1024)]
__device__ float g_xh1[Bn * 2048];   // [h1(1024), h0[1](1024)]
__device__ float g_gates[Bn * 4 * Hn];
__device__ __half g_enc_h[(size_t)Bn * Sn * En];  // fp16 enc
__device__ __half g_wae_h[(size_t)An * En];       // fp16 Wa_e

// ---------------- helpers ----------------
__device__ __forceinline__ unsigned f2tf(float f) {
    unsigned u;
    asm("cvt.rna.tf32.f32 %0, %1;" : "=r"(u) : "f"(f));
    return u;
}

__device__ __forceinline__ uint4 cvt4(float4 v) {
    uint4 o;
    o.x = f2tf(v.x); o.y = f2tf(v.y); o.z = f2tf(v.z); o.w = f2tf(v.w);
    return o;
}

__device__ __forceinline__ void mma_tf32(float* c, const unsigned* a, const unsigned* b) {
    asm volatile(
        "mma.sync.aligned.m16n8k8.row.col.f32.tf32.tf32.f32 "
        "{%0,%1,%2,%3}, {%4,%5,%6,%7}, {%8,%9}, {%0,%1,%2,%3};"
        : "+f"(c[0]), "+f"(c[1]), "+f"(c[2]), "+f"(c[3])
        : "r"(a[0]), "r"(a[1]), "r"(a[2]), "r"(a[3]), "r"(b[0]), "r"(b[1]));
}

__device__ __forceinline__ void mma_f16(float* c, const unsigned* a, const unsigned* b) {
    asm volatile(
        "mma.sync.aligned.m16n8k16.row.col.f32.f16.f16.f32 "
        "{%0,%1,%2,%3}, {%4,%5,%6,%7}, {%8,%9}, {%0,%1,%2,%3};"
        : "+f"(c[0]), "+f"(c[1]), "+f"(c[2]), "+f"(c[3])
        : "r"(a[0]), "r"(a[1]), "r"(a[2]), "r"(a[3]), "r"(b[0]), "r"(b[1]));
}

__device__ __forceinline__ void ldsm4(unsigned* r, unsigned addr) {
    asm volatile("ldmatrix.sync.aligned.m8n8.x4.shared.b16 {%0,%1,%2,%3}, [%4];"
                 : "=r"(r[0]), "=r"(r[1]), "=r"(r[2]), "=r"(r[3]) : "r"(addr));
}

__device__ __forceinline__ void cp_async16(unsigned saddr, const void* gptr) {
    asm volatile("cp.async.ca.shared.global [%0], [%1], 16;" :: "r"(saddr), "l"(gptr));
}
__device__ __forceinline__ void cp_commit() { asm volatile("cp.async.commit_group;"); }

__device__ __forceinline__ unsigned smem_u32(const void* p) {
    unsigned a;
    asm("{ .reg .u64 t; cvta.to.shared.u64 t, %1; cvt.u32.u64 %0, t; }" : "=r"(a) : "l"(p));
    return a;
}

// ---------------- fp16 pre-convert ----------------
__global__ void f16_convert(const float* __restrict__ src, __half* __restrict__ dst) {
    size_t i = ((size_t)blockIdx.x * 256 + threadIdx.x) * 8;
    float4 v0 = *(const float4*)(src + i);
    float4 v1 = *(const float4*)(src + i + 4);
    __half2* d2 = (__half2*)(dst + i);
    __half2 h0 = __floats2half2_rn(v0.x, v0.y);
    __half2 h1 = __floats2half2_rn(v0.z, v0.w);
    __half2 h2 = __floats2half2_rn(v1.x, v1.y);
    __half2 h3 = __floats2half2_rn(v1.z, v1.w);
    uint4 o;
    o.x = *(unsigned*)&h0; o.y = *(unsigned*)&h1;
    o.z = *(unsigned*)&h2; o.w = *(unsigned*)&h3;
    *(uint4*)d2 = o;
}

// ---------------- embedding gather + h staging ----------------
__global__ void embed_kernel(const int* __restrict__ input_step,
                             const float* __restrict__ emb,
                             const float* __restrict__ h0,
                             float* __restrict__ xh0,
                             float* __restrict__ xh1) {
    int b = blockIdx.x;
    int row = input_step[b];
    const float* src = emb + (size_t)row * Dn;
    for (int d = threadIdx.x; d < Dn; d += blockDim.x) {
        xh0[(size_t)b * 3072 + d] = src[d];
        xh0[(size_t)b * 3072 + 2048 + d] = h0[b * Hn + d];
        xh1[(size_t)b * 2048 + 1024 + d] = h0[Bn * Hn + b * Hn + d];
    }
}

// ---------------- tf32 TC GEMM with split-K weights (warp mma; small GEMMs) ----------------
__global__ __launch_bounds__(128) void gemm_nt_tc2(
        const float* __restrict__ Amat, int Ktot,
        const float* __restrict__ W1, int K1, const float* __restrict__ W2,
        const float* __restrict__ bias, const float* __restrict__ bias2,
        float* __restrict__ Cmat, int N) {
    __shared__ char gsm[2][16384];
    unsigned sbase = smem_u32(gsm);

    int tid = threadIdx.x;
    int w = tid >> 5, lane = tid & 31, g = lane >> 2, tig = lane & 3;
    int n0 = blockIdx.x * 64;
    int mb = (w & 1) * 32;
    int nb = (w >> 1) * 32;
    int K2 = Ktot - K1;

    int lr = tid >> 3;
    int lc16 = tid & 7;

    int rA = mb + (lane & 15);
    int akh = (lane >> 4) & 1;
    unsigned aRow0 = rA * 128, aRow1 = (rA + 16) * 128;
    int am = rA & 7;
    int rB = nb + ((lane >> 1) & 8) + (lane & 7);
    int bkh = (lane >> 3) & 1;
    unsigned bRow0 = rB * 128, bRow1 = (rB + 16) * 128;
    int bm = rB & 7;

    float acc[2][4][4];
#pragma unroll
    for (int mt = 0; mt < 2; mt++)
#pragma unroll
        for (int nf = 0; nf < 4; nf++)
#pragma unroll
            for (int r = 0; r < 4; r++) acc[mt][nf][r] = 0.f;

#define WROW(row, k) ((k) < K1 ? W1 + (size_t)(row) * K1 + (k) \
                               : W2 + (size_t)(row) * K2 + ((k) - K1))

    float4 aReg[4], wReg[4];
#pragma unroll
    for (int i = 0; i < 4; i++) {
        int row = lr + 16 * i;
        aReg[i] = *(const float4*)&Amat[(size_t)row * Ktot + lc16 * 4];
        wReg[i] = *(const float4*)(WROW(n0 + row, 0) + lc16 * 4);
    }

    int st = 0;
    for (int k0 = 0; k0 < Ktot; k0 += 32) {
#pragma unroll
        for (int i = 0; i < 4; i++) {
            int row = lr + 16 * i;
            unsigned off = row * 128 + (unsigned)((lc16 ^ (row & 7)) << 4);
            *(uint4*)(gsm[st] + off) = cvt4(aReg[i]);
            *(uint4*)(gsm[st] + 8192 + off) = cvt4(wReg[i]);
        }
        __syncthreads();

        if (k0 + 32 < Ktot) {
#pragma unroll
            for (int i = 0; i < 4; i++) {
                int row = lr + 16 * i;
                aReg[i] = *(const float4*)&Amat[(size_t)row * Ktot + k0 + 32 + lc16 * 4];
                wReg[i] = *(const float4*)(WROW(n0 + row, k0 + 32) + lc16 * 4);
            }
        }

        unsigned Ab = sbase + st * 16384;
        unsigned Wb = Ab + 8192;
#pragma unroll
        for (int ks = 0; ks < 4; ks++) {
            unsigned a0[4], a1[4], b0[4], b1[4];
            unsigned acol = ((unsigned)(ks * 2 + akh) ^ am) << 4;
            unsigned bcol = ((unsigned)(ks * 2 + bkh) ^ bm) << 4;
            ldsm4(a0, Ab + aRow0 + acol);
            ldsm4(a1, Ab + aRow1 + acol);
            ldsm4(b0, Wb + bRow0 + bcol);
            ldsm4(b1, Wb + bRow1 + bcol);
            mma_tf32(acc[0][0], a0, b0);
            mma_tf32(acc[0][1], a0, b0 + 2);
            mma_tf32(acc[1][0], a1, b0);
            mma_tf32(acc[1][1], a1, b0 + 2);
            mma_tf32(acc[0][2], a0, b1);
            mma_tf32(acc[0][3], a0, b1 + 2);
            mma_tf32(acc[1][2], a1, b1);
            mma_tf32(acc[1][3], a1, b1 + 2);
        }
        __syncthreads();
        st ^= 1;
    }
#undef WROW

#pragma unroll
    for (int mt = 0; mt < 2; mt++) {
        int m0i = mb + mt * 16 + g;
        int m1i = m0i + 8;
#pragma unroll
        for (int nf = 0; nf < 4; nf++) {
            int n = n0 + nb + nf * 8 + 2 * tig;
            float badd0 = 0.f, badd1 = 0.f;
            if (bias)  { badd0 += bias[n];  badd1 += bias[n + 1]; }
            if (bias2) { badd0 += bias2[n]; badd1 += bias2[n + 1]; }
            Cmat[(size_t)m0i * N + n]     = acc[mt][nf][0] + badd0;
            Cmat[(size_t)m0i * N + n + 1] = acc[mt][nf][1] + badd1;
            Cmat[(size_t)m1i * N + n]     = acc[mt][nf][2] + badd0;
            Cmat[(size_t)m1i * N + n + 1] = acc[mt][nf][3] + badd1;
        }
    }
}

// ---------------- score init ----------------
__global__ void score_init_kernel(const float* __restrict__ bva, float* __restrict__ score) {
    int i = blockIdx.x * blockDim.x + threadIdx.x;
    if (i < Bn * Sn) score[i] = bva[0];
}

// ---------------- fused attention score GEMM (fp16 m16n8k16) ----------------
// BM=128, BN=128, BK=64 (fp16), 512 threads (16 warps: 4m x 4n, warp tile 32x32).
// 3-stage cp.async pipeline; rows of 64 fp16 = 128B, same XOR swizzle as before.
// grid: (A/128 = 8, BS/128 = 512), x fastest -> enc tile L2 reuse.
__global__ __launch_bounds__(512) void score_gemm_mma(
        const __half* __restrict__ enc_h, const __half* __restrict__ wae_h,
        const float* __restrict__ ba_e, const float* __restrict__ q,
        const float* __restrict__ va, float* __restrict__ score) {
    extern __shared__ char smem_raw[];
    unsigned sbase = smem_u32(smem_raw);
    const unsigned STAGE = 32768;  // A 16KB + W 16KB (fp16)
    float* qb  = (float*)(smem_raw + 3 * STAGE);
    float* vas = qb + 128;

    int tid = threadIdx.x;
    int w = tid >> 5, lane = tid & 31, g = lane >> 2, tig = lane & 3;
    int n0 = blockIdx.x * 128;
    int m0 = blockIdx.y * 128;
    int b = m0 >> 10;
    int mb = (w >> 2) * 32;
    int nb = (w & 3) * 32;

    if (tid < 128) {
        qb[tid]  = q[b * An + n0 + tid] + ba_e[n0 + tid];
        vas[tid] = va[n0 + tid];
    }

    int crow = tid >> 3;    // 0..63
    int ccol = tid & 7;     // 16B chunk (16 fp16 per row chunk... 8 chunks/row)
    const __half* encp = enc_h + (size_t)m0 * En;
    const __half* waep = wae_h + (size_t)n0 * En;

    // ldmatrix geometry (b16-native now)
    int rA = mb + (lane & 15);
    int akh = (lane >> 4) & 1;
    unsigned aRow0 = rA * 128, aRow1 = (rA + 16) * 128;
    int am = rA & 7;
    int rB = nb + ((lane >> 1) & 8) + (lane & 7);
    int bkh = (lane >> 3) & 1;
    unsigned bRow0 = rB * 128, bRow1 = (rB + 16) * 128;
    int bm = rB & 7;

    float acc[2][4][4];
#pragma unroll
    for (int mt = 0; mt < 2; mt++)
#pragma unroll
        for (int nf = 0; nf < 4; nf++)
#pragma unroll
            for (int r = 0; r < 4; r++) acc[mt][nf][r] = 0.f;

#define PREFETCH(st, k0)                                                          \
    do {                                                                          \
        unsigned Ad = sbase + (st) * STAGE;                                       \
        unsigned Wd = Ad + 16384;                                                 \
        _Pragma("unroll")                                                         \
        for (int i = 0; i < 2; i++) {                                             \
            int row = crow + i * 64;                                              \
            cp_async16(Ad + row * 128 + ((ccol ^ (row & 7)) << 4),                \
                       encp + (size_t)row * En + (k0) + ccol * 8);                \
        }                                                                         \
        _Pragma("unroll")                                                         \
        for (int i = 0; i < 2; i++) {                                             \
            int row = crow + i * 64;                                              \
            cp_async16(Wd + row * 128 + ((ccol ^ (row & 7)) << 4),                \
                       waep + (size_t)row * En + (k0) + ccol * 8);                \
        }                                                                         \
        cp_commit();                                                              \
    } while (0)

    PREFETCH(0, 0);
    PREFETCH(1, 64);

    const int NT = En / 64;  // 16 iterations, K=64 fp16 per iter
    int st = 0;
    for (int it = 0; it < NT; it++) {
        if (it == NT - 1) asm volatile("cp.async.wait_group 0;");
        else              asm volatile("cp.async.wait_group 1;");
        __syncthreads();

        unsigned Ab = sbase + st * STAGE;
        unsigned Wb = Ab + 16384;
#pragma unroll
        for (int ks = 0; ks < 4; ks++) {  // each ks = k16
            unsigned a0[4], a1[4], b0[4], b1[4];
            unsigned acol = ((unsigned)(ks * 2 + akh) ^ am) << 4;
            unsigned bcol = ((unsigned)(ks * 2 + bkh) ^ bm) << 4;
            ldsm4(a0, Ab + aRow0 + acol);   // rows mb..mb+15, k16
            ldsm4(a1, Ab + aRow1 + acol);   // rows mb+16..mb+31
            ldsm4(b0, Wb + bRow0 + bcol);   // n rows nb..nb+15 (frags nf0,nf1)
            ldsm4(b1, Wb + bRow1 + bcol);   // n rows nb+16..nb+31 (nf2,nf3)
            mma_f16(acc[0][0], a0, b0);
            mma_f16(acc[0][1], a0, b0 + 2);
            mma_f16(acc[1][0], a1, b0);
            mma_f16(acc[1][1], a1, b0 + 2);
            mma_f16(acc[0][2], a0, b1);
            mma_f16(acc[0][3], a0, b1 + 2);
            mma_f16(acc[1][2], a1, b1);
            mma_f16(acc[1][3], a1, b1 + 2);
        }

        int pf = it + 2;
        if (pf < NT) PREFETCH(pf % 3, pf * 64);
        st = (st + 1 == 3) ? 0 : st + 1;
    }
#undef PREFETCH

    // epilogue: tanh + va-weighted row reduction (m16n8 C layout unchanged)
#pragma unroll
    for (int mt = 0; mt < 2; mt++) {
        float sumlo = 0.f, sumhi = 0.f;
#pragma unroll
        for (int nf = 0; nf < 4; nf++) {
            int nl = nb + nf * 8 + 2 * tig;
            float q0 = qb[nl], q1 = qb[nl + 1];
            float v0 = vas[nl], v1 = vas[nl + 1];
            sumlo += v0 * tanhf(acc[mt][nf][0] + q0) + v1 * tanhf(acc[mt][nf][1] + q1);
            sumhi += v0 * tanhf(acc[mt][nf][2] + q0) + v1 * tanhf(acc[mt][nf][3] + q1);
        }
        sumlo += __shfl_xor_sync(0xffffffffu, sumlo, 1);
        sumlo += __shfl_xor_sync(0xffffffffu, sumlo, 2);
        sumhi += __shfl_xor_sync(0xffffffffu, sumhi, 1);
        sumhi += __shfl_xor_sync(0xffffffffu, sumhi, 2);
        if (tig == 0) {
            int r = m0 + mb + mt * 16 + g;
            atomicAdd(&score[r], sumlo);
            atomicAdd(&score[r + 8], sumhi);
        }
    }
}

// ---------------- softmax ----------------
__global__ void softmax_kernel(const float* __restrict__ score, float* __restrict__ attn) {
    __shared__ float sh[Sn];
    __shared__ float red[256];
    int b = blockIdx.x;
    int tid = threadIdx.x;

    float lmax = -3.4e38f;
    for (int s = tid; s < Sn; s += 256) {
        float v = score[b * Sn + s];
        sh[s] = v;
        lmax = fmaxf(lmax, v);
    }
    red[tid] = lmax;
    __syncthreads();
    for (int off = 128; off > 0; off >>= 1) {
        if (tid < off) red[tid] = fmaxf(red[tid], red[tid + off]);
        __syncthreads();
    }
    float m = red[0];
    __syncthreads();

    float lsum = 0.f;
    for (int s = tid; s < Sn; s += 256) {
        float e = expf(sh[s] - m);
        sh[s] = e;
        lsum += e;
    }
    red[tid] = lsum;
    __syncthreads();
    for (int off = 128; off > 0; off >>= 1) {
        if (tid < off) red[tid] += red[tid + off];
        __syncthreads();
    }
    float inv = 1.f / red[0];
    __syncthreads();

    for (int s = tid; s < Sn; s += 256) attn[b * Sn + s] = sh[s] * inv;
}

// ---------------- context = attn @ enc (writes into xh0 middle slot) ----------------
__global__ void context_kernel(const float* __restrict__ enc,
                               const float* __restrict__ attn,
                               float* __restrict__ xh0) {
    __shared__ float w[Sn];
    int b = blockIdx.x;
    int e = blockIdx.y * 256 + threadIdx.x;
    for (int s = threadIdx.x; s < Sn; s += 256) w[s] = attn[b * Sn + s];
    __syncthreads();
    const float* ep = enc + (size_t)b * Sn * En + e;
    float acc = 0.f;
#pragma unroll 8
    for (int s = 0; s < Sn; s++) acc += w[s] * ep[(size_t)s * En];
    xh0[(size_t)b * 3072 + 1024 + e] = acc;
}

// ---------------- LSTM pointwise ----------------
__global__ void lstm_pointwise(const float* __restrict__ gates,
                               const float* __restrict__ cprev,
                               float* __restrict__ hout,
                               float* __restrict__ cout,
                               float* __restrict__ hcopy, int hstride) {
    int idx = blockIdx.x * 256 + threadIdx.x;
    if (idx >= Bn * Hn) return;
    int b = idx >> 10;
    int h = idx & 1023;
    const float* g = gates + (size_t)b * 4 * Hn;
    float ig = 1.f / (1.f + expf(-g[h]));
    float fg = 1.f / (1.f + expf(-g[Hn + h]));
    float gg = tanhf(g[2 * Hn + h]);
    float og = 1.f / (1.f + expf(-g[3 * Hn + h]));
    float c = fg * cprev[idx] + ig * gg;
    float hv = og * tanhf(c);
    hout[idx] = hv;
    cout[idx] = c;
    if (hcopy) hcopy[(size_t)b * hstride + h] = hv;
}

// ---------------- launcher ----------------
extern "C" void kernel_launch(void* const* d_in, const int* in_sizes, int n_in,
                              void* d_out, int out_size) {
    const int*   input_step = (const int*)d_in[0];
    const float* h0    = (const float*)d_in[1];
    const float* c0    = (const float*)d_in[2];
    const float* enc   = (const float*)d_in[3];
    const float* emb   = (const float*)d_in[4];
    const float* Wa_h  = (const float*)d_in[5];
    const float* ba_h  = (const float*)d_in[6];
    const float* Wa_e  = (const float*)d_in[7];
    const float* ba_e  = (const float*)d_in[8];
    const float* va    = (const float*)d_in[9];
    const float* bva   = (const float*)d_in[10];
    const float* Wih0  = (const float*)d_in[11];
    const float* Whh0  = (const float*)d_in[12];
    const float* bih0  = (const float*)d_in[13];
    const float* bhh0  = (const float*)d_in[14];
    const float* Wih1  = (const float*)d_in[15];
    const float* Whh1  = (const float*)d_in[16];
    const float* bih1  = (const float*)d_in[17];
    const float* bhh1  = (const float*)d_in[18];
    const float* Wout  = (const float*)d_in[19];
    const float* bout  = (const float*)d_in[20];

    float* out = (float*)d_out;
    float* out_logits = out;
    float* out_h      = out_logits + Bn * Vn;
    float* out_c      = out_h + 2 * Bn * Hn;
    float* out_attn   = out_c + 2 * Bn * Hn;

    float* q_buf;     cudaGetSymbolAddress((void**)&q_buf, g_q);
    float* score_buf; cudaGetSymbolAddress((void**)&score_buf, g_score);
    float* xh0;       cudaGetSymbolAddress((void**)&xh0, g_xh0);
    float* xh1;       cudaGetSymbolAddress((void**)&xh1, g_xh1);
    float* gates_buf; cudaGetSymbolAddress((void**)&gates_buf, g_gates);
    __half* enc_h;    cudaGetSymbolAddress((void**)&enc_h, g_enc_h);
    __half* wae_h;    cudaGetSymbolAddress((void**)&wae_h, g_wae_h);

    const int score_smem = 3 * 32768 + 1024;  // 99328
    cudaFuncSetAttribute(score_gemm_mma, cudaFuncAttributeMaxDynamicSharedMemorySize,
                         score_smem);

    // 0. pre-convert enc and Wa_e to fp16
    f16_convert<<<(Bn * Sn * En) / 2048, 256>>>(enc, enc_h);
    f16_convert<<<(An * En) / 2048, 256>>>(Wa_e, wae_h);

    // 1. embedding gather + h0 staging
    embed_kernel<<<Bn, 256>>>(input_step, emb, h0, xh0, xh1);

    // 2. q = h0[1] @ Wa_h^T + ba_h
    gemm_nt_tc2<<<An / 64, 128>>>(h0 + Bn * Hn, Hn, Wa_h, Hn, nullptr,
                                  ba_h, nullptr, q_buf, An);

    // 3. fused fp16 score GEMM
    score_init_kernel<<<(Bn * Sn + 255) / 256, 256>>>(bva, score_buf);
    {
        dim3 grid(An / 128, Bn * Sn / 128);
        score_gemm_mma<<<grid, 512, score_smem>>>(enc_h, wae_h, ba_e, q_buf, va, score_buf);
    }

    // 4. softmax
    softmax_kernel<<<Bn, 256>>>(score_buf, out_attn);

    // 5. context -> xh0[:, 1024:2048]
    {
        dim3 grid(Bn, En / 256);
        context_kernel<<<grid, 256>>>(enc, out_attn, xh0);
    }

    // 6. LSTM layer 0: gates = [x, h0[0]] @ [Wih0; Whh0]^T + biases
    gemm_nt_tc2<<<4 * Hn / 64, 128>>>(xh0, 3072, Wih0, Dn + En, Whh0,
                                      bih0, bhh0, gates_buf, 4 * Hn);
    lstm_pointwise<<<(Bn * Hn + 255) / 256, 256>>>(gates_buf, c0, out_h, out_c,
                                                   xh1, 2048);

    // 7. LSTM layer 1: gates = [h1, h0[1]] @ [Wih1; Whh1]^T + biases
    gemm_nt_tc2<<<4 * Hn / 64, 128>>>(xh1, 2048, Wih1, Hn, Whh1,
                                      bih1, bhh1, gates_buf, 4 * Hn);
    lstm_pointwise<<<(Bn * Hn + 255) / 256, 256>>>(gates_buf, c0 + Bn * Hn,
                                                   out_h + Bn * Hn, out_c + Bn * Hn,
                                                   nullptr, 0);

    // 8. logits = h2 @ Wout^T + bout
    gemm_nt_tc2<<<Vn / 64, 128>>>(out_h + Bn * Hn, Hn, Wout, Hn, nullptr,
                                  bout, nullptr, out_logits, Vn);
}

// round 14
// speedup vs baseline: 1.9942x; 1.0537x over previous
#include <cuda_runtime.h>
#include <cuda_bf16.h>
#include <cuda_fp16.h>

#define Bn 64
#define Sn 1024
#define Vn 32000
#define Dn 1024
#define Hn 1024
#define En 1024
#define An 1024

// ---------------- scratch (no allocs allowed) ----------------
__device__ float g_q[Bn * An];
__device__ float g_score[Bn * Sn];
__device__ float g_xh0[Bn * 3072];   // [embedded(1024), context(1024), h0[0](1024)]
__device__ float g_xh1[Bn * 2048];   // [h1(1024), h0[1](1024)]
__device__ float g_gates[Bn * 4 * Hn];
__device__ __half g_enc_h[(size_t)Bn * Sn * En];  // fp16 enc
__device__ __half g_wae_h[(size_t)An * En];       // fp16 Wa_e

// ---------------- helpers ----------------
__device__ __forceinline__ unsigned f2tf(float f) {
    unsigned u;
    asm("cvt.rna.tf32.f32 %0, %1;" : "=r"(u) : "f"(f));
    return u;
}

__device__ __forceinline__ uint4 cvt4(float4 v) {
    uint4 o;
    o.x = f2tf(v.x); o.y = f2tf(v.y); o.z = f2tf(v.z); o.w = f2tf(v.w);
    return o;
}

__device__ __forceinline__ void mma_tf32(float* c, const unsigned* a, const unsigned* b) {
    asm volatile(
        "mma.sync.aligned.m16n8k8.row.col.f32.tf32.tf32.f32 "
        "{%0,%1,%2,%3}, {%4,%5,%6,%7}, {%8,%9}, {%0,%1,%2,%3};"
        : "+f"(c[0]), "+f"(c[1]), "+f"(c[2]), "+f"(c[3])
        : "r"(a[0]), "r"(a[1]), "r"(a[2]), "r"(a[3]), "r"(b[0]), "r"(b[1]));
}

__device__ __forceinline__ void mma_f16(float* c, const unsigned* a, const unsigned* b) {
    asm volatile(
        "mma.sync.aligned.m16n8k16.row.col.f32.f16.f16.f32 "
        "{%0,%1,%2,%3}, {%4,%5,%6,%7}, {%8,%9}, {%0,%1,%2,%3};"
        : "+f"(c[0]), "+f"(c[1]), "+f"(c[2]), "+f"(c[3])
        : "r"(a[0]), "r"(a[1]), "r"(a[2]), "r"(a[3]), "r"(b[0]), "r"(b[1]));
}

__device__ __forceinline__ void ldsm4(unsigned* r, unsigned addr) {
    asm volatile("ldmatrix.sync.aligned.m8n8.x4.shared.b16 {%0,%1,%2,%3}, [%4];"
                 : "=r"(r[0]), "=r"(r[1]), "=r"(r[2]), "=r"(r[3]) : "r"(addr));
}

__device__ __forceinline__ void cp_async16(unsigned saddr, const void* gptr) {
    asm volatile("cp.async.ca.shared.global [%0], [%1], 16;" :: "r"(saddr), "l"(gptr));
}
__device__ __forceinline__ void cp_commit() { asm volatile("cp.async.commit_group;"); }

__device__ __forceinline__ unsigned smem_u32(const void* p) {
    unsigned a;
    asm("{ .reg .u64 t; cvta.to.shared.u64 t, %1; cvt.u32.u64 %0, t; }" : "=r"(a) : "l"(p));
    return a;
}

// ---------------- fp16 pre-convert ----------------
__global__ void f16_convert(const float* __restrict__ src, __half* __restrict__ dst) {
    size_t i = ((size_t)blockIdx.x * 256 + threadIdx.x) * 8;
    float4 v0 = *(const float4*)(src + i);
    float4 v1 = *(const float4*)(src + i + 4);
    __half2 h0 = __floats2half2_rn(v0.x, v0.y);
    __half2 h1 = __floats2half2_rn(v0.z, v0.w);
    __half2 h2 = __floats2half2_rn(v1.x, v1.y);
    __half2 h3 = __floats2half2_rn(v1.z, v1.w);
    uint4 o;
    o.x = *(unsigned*)&h0; o.y = *(unsigned*)&h1;
    o.z = *(unsigned*)&h2; o.w = *(unsigned*)&h3;
    *(uint4*)(dst + i) = o;
}

// ---------------- embedding gather + h staging ----------------
__global__ void embed_kernel(const int* __restrict__ input_step,
                             const float* __restrict__ emb,
                             const float* __restrict__ h0,
                             float* __restrict__ xh0,
                             float* __restrict__ xh1) {
    int b = blockIdx.x;
    int row = input_step[b];
    const float* src = emb + (size_t)row * Dn;
    for (int d = threadIdx.x; d < Dn; d += blockDim.x) {
        xh0[(size_t)b * 3072 + d] = src[d];
        xh0[(size_t)b * 3072 + 2048 + d] = h0[b * Hn + d];
        xh1[(size_t)b * 2048 + 1024 + d] = h0[Bn * Hn + b * Hn + d];
    }
}

// ---------------- tf32 TC GEMM with split-K weights (warp mma; small GEMMs) ----------------
__global__ __launch_bounds__(128) void gemm_nt_tc2(
        const float* __restrict__ Amat, int Ktot,
        const float* __restrict__ W1, int K1, const float* __restrict__ W2,
        const float* __restrict__ bias, const float* __restrict__ bias2,
        float* __restrict__ Cmat, int N) {
    __shared__ char gsm[2][16384];
    unsigned sbase = smem_u32(gsm);

    int tid = threadIdx.x;
    int w = tid >> 5, lane = tid & 31, g = lane >> 2, tig = lane & 3;
    int n0 = blockIdx.x * 64;
    int mb = (w & 1) * 32;
    int nb = (w >> 1) * 32;
    int K2 = Ktot - K1;

    int lr = tid >> 3;
    int lc16 = tid & 7;

    int rA = mb + (lane & 15);
    int akh = (lane >> 4) & 1;
    unsigned aRow0 = rA * 128, aRow1 = (rA + 16) * 128;
    int am = rA & 7;
    int rB = nb + ((lane >> 1) & 8) + (lane & 7);
    int bkh = (lane >> 3) & 1;
    unsigned bRow0 = rB * 128, bRow1 = (rB + 16) * 128;
    int bm = rB & 7;

    float acc[2][4][4];
#pragma unroll
    for (int mt = 0; mt < 2; mt++)
#pragma unroll
        for (int nf = 0; nf < 4; nf++)
#pragma unroll
            for (int r = 0; r < 4; r++) acc[mt][nf][r] = 0.f;

#define WROW(row, k) ((k) < K1 ? W1 + (size_t)(row) * K1 + (k) \
                               : W2 + (size_t)(row) * K2 + ((k) - K1))

    float4 aReg[4], wReg[4];
#pragma unroll
    for (int i = 0; i < 4; i++) {
        int row = lr + 16 * i;
        aReg[i] = *(const float4*)&Amat[(size_t)row * Ktot + lc16 * 4];
        wReg[i] = *(const float4*)(WROW(n0 + row, 0) + lc16 * 4);
    }

    int st = 0;
    for (int k0 = 0; k0 < Ktot; k0 += 32) {
#pragma unroll
        for (int i = 0; i < 4; i++) {
            int row = lr + 16 * i;
            unsigned off = row * 128 + (unsigned)((lc16 ^ (row & 7)) << 4);
            *(uint4*)(gsm[st] + off) = cvt4(aReg[i]);
            *(uint4*)(gsm[st] + 8192 + off) = cvt4(wReg[i]);
        }
        __syncthreads();

        if (k0 + 32 < Ktot) {
#pragma unroll
            for (int i = 0; i < 4; i++) {
                int row = lr + 16 * i;
                aReg[i] = *(const float4*)&Amat[(size_t)row * Ktot + k0 + 32 + lc16 * 4];
                wReg[i] = *(const float4*)(WROW(n0 + row, k0 + 32) + lc16 * 4);
            }
        }

        unsigned Ab = sbase + st * 16384;
        unsigned Wb = Ab + 8192;
#pragma unroll
        for (int ks = 0; ks < 4; ks++) {
            unsigned a0[4], a1[4], b0[4], b1[4];
            unsigned acol = ((unsigned)(ks * 2 + akh) ^ am) << 4;
            unsigned bcol = ((unsigned)(ks * 2 + bkh) ^ bm) << 4;
            ldsm4(a0, Ab + aRow0 + acol);
            ldsm4(a1, Ab + aRow1 + acol);
            ldsm4(b0, Wb + bRow0 + bcol);
            ldsm4(b1, Wb + bRow1 + bcol);
            mma_tf32(acc[0][0], a0, b0);
            mma_tf32(acc[0][1], a0, b0 + 2);
            mma_tf32(acc[1][0], a1, b0);
            mma_tf32(acc[1][1], a1, b0 + 2);
            mma_tf32(acc[0][2], a0, b1);
            mma_tf32(acc[0][3], a0, b1 + 2);
            mma_tf32(acc[1][2], a1, b1);
            mma_tf32(acc[1][3], a1, b1 + 2);
        }
        __syncthreads();
        st ^= 1;
    }
#undef WROW

#pragma unroll
    for (int mt = 0; mt < 2; mt++) {
        int m0i = mb + mt * 16 + g;
        int m1i = m0i + 8;
#pragma unroll
        for (int nf = 0; nf < 4; nf++) {
            int n = n0 + nb + nf * 8 + 2 * tig;
            float badd0 = 0.f, badd1 = 0.f;
            if (bias)  { badd0 += bias[n];  badd1 += bias[n + 1]; }
            if (bias2) { badd0 += bias2[n]; badd1 += bias2[n + 1]; }
            Cmat[(size_t)m0i * N + n]     = acc[mt][nf][0] + badd0;
            Cmat[(size_t)m0i * N + n + 1] = acc[mt][nf][1] + badd1;
            Cmat[(size_t)m1i * N + n]     = acc[mt][nf][2] + badd0;
            Cmat[(size_t)m1i * N + n + 1] = acc[mt][nf][3] + badd1;
        }
    }
}

// ---------------- score init ----------------
__global__ void score_init_kernel(const float* __restrict__ bva, float* __restrict__ score) {
    int i = blockIdx.x * blockDim.x + threadIdx.x;
    if (i < Bn * Sn) score[i] = bva[0];
}

// ---------------- fused attention score GEMM (fp16 m16n8k16, wide warp tiles) ----------------
// BM=128, BN=128, BK=64 fp16. 256 threads = 8 warps (4m x 2n), warp tile 32x64.
// 3-stage cp.async pipeline; rows of 64 fp16 = 128B, XOR swizzle.
// grid: (A/128 = 8, BS/128 = 512), x fastest -> enc tile L2 reuse.
__global__ __launch_bounds__(256) void score_gemm_mma(
        const __half* __restrict__ enc_h, const __half* __restrict__ wae_h,
        const float* __restrict__ ba_e, const float* __restrict__ q,
        const float* __restrict__ va, float* __restrict__ score) {
    extern __shared__ char smem_raw[];
    unsigned sbase = smem_u32(smem_raw);
    const unsigned STAGE = 32768;  // A 16KB + W 16KB (fp16)
    float* qb  = (float*)(smem_raw + 3 * STAGE);
    float* vas = qb + 128;

    int tid = threadIdx.x;
    int w = tid >> 5, lane = tid & 31, g = lane >> 2, tig = lane & 3;
    int n0 = blockIdx.x * 128;
    int m0 = blockIdx.y * 128;
    int b = m0 >> 10;
    int mb = (w >> 1) * 32;    // 4 m-warps
    int nb = (w & 1) * 64;     // 2 n-warps, 64 cols each

    if (tid < 128) {
        qb[tid]  = q[b * An + n0 + tid] + ba_e[n0 + tid];
        vas[tid] = va[n0 + tid];
    }

    int crow = tid >> 3;    // 0..31
    int ccol = tid & 7;
    const __half* encp = enc_h + (size_t)m0 * En;
    const __half* waep = wae_h + (size_t)n0 * En;

    // ldmatrix geometry
    int rA = mb + (lane & 15);
    int akh = (lane >> 4) & 1;
    unsigned aRow0 = rA * 128, aRow1 = (rA + 16) * 128;
    int am = rA & 7;
    int rBb = ((lane >> 1) & 8) + (lane & 7);
    int bkh = (lane >> 3) & 1;
    unsigned bRow[4];
    int bm[4];
#pragma unroll
    for (int j = 0; j < 4; j++) {
        int r = nb + 16 * j + rBb;
        bRow[j] = r * 128;
        bm[j] = r & 7;
    }

    float acc[2][8][4];
#pragma unroll
    for (int mt = 0; mt < 2; mt++)
#pragma unroll
        for (int nf = 0; nf < 8; nf++)
#pragma unroll
            for (int r = 0; r < 4; r++) acc[mt][nf][r] = 0.f;

#define PREFETCH(st, k0)                                                          \
    do {                                                                          \
        unsigned Ad = sbase + (st) * STAGE;                                       \
        unsigned Wd = Ad + 16384;                                                 \
        _Pragma("unroll")                                                         \
        for (int i = 0; i < 4; i++) {                                             \
            int row = crow + i * 32;                                              \
            cp_async16(Ad + row * 128 + ((ccol ^ (row & 7)) << 4),                \
                       encp + (size_t)row * En + (k0) + ccol * 8);                \
        }                                                                         \
        _Pragma("unroll")                                                         \
        for (int i = 0; i < 4; i++) {                                             \
            int row = crow + i * 32;                                              \
            cp_async16(Wd + row * 128 + ((ccol ^ (row & 7)) << 4),                \
                       waep + (size_t)row * En + (k0) + ccol * 8);                \
        }                                                                         \
        cp_commit();                                                              \
    } while (0)

    PREFETCH(0, 0);
    PREFETCH(1, 64);

    const int NT = En / 64;  // 16 iterations
    int st = 0;
    for (int it = 0; it < NT; it++) {
        if (it == NT - 1) asm volatile("cp.async.wait_group 0;");
        else              asm volatile("cp.async.wait_group 1;");
        __syncthreads();

        unsigned Ab = sbase + st * STAGE;
        unsigned Wb = Ab + 16384;
#pragma unroll
        for (int ks = 0; ks < 4; ks++) {
            unsigned a0[4], a1[4];
            unsigned acol = ((unsigned)(ks * 2 + akh) ^ am) << 4;
            ldsm4(a0, Ab + aRow0 + acol);
            ldsm4(a1, Ab + aRow1 + acol);
#pragma unroll
            for (int j = 0; j < 4; j++) {
                unsigned bf[4];
                unsigned bcol = ((unsigned)(ks * 2 + bkh) ^ bm[j]) << 4;
                ldsm4(bf, Wb + bRow[j] + bcol);
                mma_f16(acc[0][2 * j],     a0, bf);
                mma_f16(acc[0][2 * j + 1], a0, bf + 2);
                mma_f16(acc[1][2 * j],     a1, bf);
                mma_f16(acc[1][2 * j + 1], a1, bf + 2);
            }
        }

        int pf = it + 2;
        if (pf < NT) PREFETCH(pf % 3, pf * 64);
        st = (st + 1 == 3) ? 0 : st + 1;
    }
#undef PREFETCH

    // epilogue: tanh + va-weighted row reduction
#pragma unroll
    for (int mt = 0; mt < 2; mt++) {
        float sumlo = 0.f, sumhi = 0.f;
#pragma unroll
        for (int nf = 0; nf < 8; nf++) {
            int nl = nb + nf * 8 + 2 * tig;
            float q0 = qb[nl], q1 = qb[nl + 1];
            float v0 = vas[nl], v1 = vas[nl + 1];
            sumlo += v0 * tanhf(acc[mt][nf][0] + q0) + v1 * tanhf(acc[mt][nf][1] + q1);
            sumhi += v0 * tanhf(acc[mt][nf][2] + q0) + v1 * tanhf(acc[mt][nf][3] + q1);
        }
        sumlo += __shfl_xor_sync(0xffffffffu, sumlo, 1);
        sumlo += __shfl_xor_sync(0xffffffffu, sumlo, 2);
        sumhi += __shfl_xor_sync(0xffffffffu, sumhi, 1);
        sumhi += __shfl_xor_sync(0xffffffffu, sumhi, 2);
        if (tig == 0) {
            int r = m0 + mb + mt * 16 + g;
            atomicAdd(&score[r], sumlo);
            atomicAdd(&score[r + 8], sumhi);
        }
    }
}

// ---------------- softmax ----------------
__global__ void softmax_kernel(const float* __restrict__ score, float* __restrict__ attn) {
    __shared__ float sh[Sn];
    __shared__ float red[256];
    int b = blockIdx.x;
    int tid = threadIdx.x;

    float lmax = -3.4e38f;
    for (int s = tid; s < Sn; s += 256) {
        float v = score[b * Sn + s];
        sh[s] = v;
        lmax = fmaxf(lmax, v);
    }
    red[tid] = lmax;
    __syncthreads();
    for (int off = 128; off > 0; off >>= 1) {
        if (tid < off) red[tid] = fmaxf(red[tid], red[tid + off]);
        __syncthreads();
    }
    float m = red[0];
    __syncthreads();

    float lsum = 0.f;
    for (int s = tid; s < Sn; s += 256) {
        float e = expf(sh[s] - m);
        sh[s] = e;
        lsum += e;
    }
    red[tid] = lsum;
    __syncthreads();
    for (int off = 128; off > 0; off >>= 1) {
        if (tid < off) red[tid] += red[tid + off];
        __syncthreads();
    }
    float inv = 1.f / red[0];
    __syncthreads();

    for (int s = tid; s < Sn; s += 256) attn[b * Sn + s] = sh[s] * inv;
}

// ---------------- context = attn @ enc_h (fp16 enc, fp32 accumulate) ----------------
__global__ void context_kernel(const __half* __restrict__ enc_h,
                               const float* __restrict__ attn,
                               float* __restrict__ xh0) {
    __shared__ float w[Sn];
    int b = blockIdx.x;
    int e = blockIdx.y * 256 + threadIdx.x;
    for (int s = threadIdx.x; s < Sn; s += 256) w[s] = attn[b * Sn + s];
    __syncthreads();
    const __half* ep = enc_h + (size_t)b * Sn * En + e;
    float acc = 0.f;
#pragma unroll 8
    for (int s = 0; s < Sn; s++) acc += w[s] * __half2float(ep[(size_t)s * En]);
    xh0[(size_t)b * 3072 + 1024 + e] = acc;
}

// ---------------- LSTM pointwise ----------------
__global__ void lstm_pointwise(const float* __restrict__ gates,
                               const float* __restrict__ cprev,
                               float* __restrict__ hout,
                               float* __restrict__ cout,
                               float* __restrict__ hcopy, int hstride) {
    int idx = blockIdx.x * 256 + threadIdx.x;
    if (idx >= Bn * Hn) return;
    int b = idx >> 10;
    int h = idx & 1023;
    const float* g = gates + (size_t)b * 4 * Hn;
    float ig = 1.f / (1.f + expf(-g[h]));
    float fg = 1.f / (1.f + expf(-g[Hn + h]));
    float gg = tanhf(g[2 * Hn + h]);
    float og = 1.f / (1.f + expf(-g[3 * Hn + h]));
    float c = fg * cprev[idx] + ig * gg;
    float hv = og * tanhf(c);
    hout[idx] = hv;
    cout[idx] = c;
    if (hcopy) hcopy[(size_t)b * hstride + h] = hv;
}

// ---------------- launcher ----------------
extern "C" void kernel_launch(void* const* d_in, const int* in_sizes, int n_in,
                              void* d_out, int out_size) {
    const int*   input_step = (const int*)d_in[0];
    const float* h0    = (const float*)d_in[1];
    const float* c0    = (const float*)d_in[2];
    const float* enc   = (const float*)d_in[3];
    const float* emb   = (const float*)d_in[4];
    const float* Wa_h  = (const float*)d_in[5];
    const float* ba_h  = (const float*)d_in[6];
    const float* Wa_e  = (const float*)d_in[7];
    const float* ba_e  = (const float*)d_in[8];
    const float* va    = (const float*)d_in[9];
    const float* bva   = (const float*)d_in[10];
    const float* Wih0  = (const float*)d_in[11];
    const float* Whh0  = (const float*)d_in[12];
    const float* bih0  = (const float*)d_in[13];
    const float* bhh0  = (const float*)d_in[14];
    const float* Wih1  = (const float*)d_in[15];
    const float* Whh1  = (const float*)d_in[16];
    const float* bih1  = (const float*)d_in[17];
    const float* bhh1  = (const float*)d_in[18];
    const float* Wout  = (const float*)d_in[19];
    const float* bout  = (const float*)d_in[20];

    float* out = (float*)d_out;
    float* out_logits = out;
    float* out_h      = out_logits + Bn * Vn;
    float* out_c      = out_h + 2 * Bn * Hn;
    float* out_attn   = out_c + 2 * Bn * Hn;

    float* q_buf;     cudaGetSymbolAddress((void**)&q_buf, g_q);
    float* score_buf; cudaGetSymbolAddress((void**)&score_buf, g_score);
    float* xh0;       cudaGetSymbolAddress((void**)&xh0, g_xh0);
    float* xh1;       cudaGetSymbolAddress((void**)&xh1, g_xh1);
    float* gates_buf; cudaGetSymbolAddress((void**)&gates_buf, g_gates);
    __half* enc_h;    cudaGetSymbolAddress((void**)&enc_h, g_enc_h);
    __half* wae_h;    cudaGetSymbolAddress((void**)&wae_h, g_wae_h);

    const int score_smem = 3 * 32768 + 1024;  // 99328
    cudaFuncSetAttribute(score_gemm_mma, cudaFuncAttributeMaxDynamicSharedMemorySize,
                         score_smem);

    // 0. pre-convert enc and Wa_e to fp16
    f16_convert<<<(Bn * Sn * En) / 2048, 256>>>(enc, enc_h);
    f16_convert<<<(An * En) / 2048, 256>>>(Wa_e, wae_h);

    // 1. embedding gather + h0 staging
    embed_kernel<<<Bn, 256>>>(input_step, emb, h0, xh0, xh1);

    // 2. q = h0[1] @ Wa_h^T + ba_h
    gemm_nt_tc2<<<An / 64, 128>>>(h0 + Bn * Hn, Hn, Wa_h, Hn, nullptr,
                                  ba_h, nullptr, q_buf, An);

    // 3. fused fp16 score GEMM
    score_init_kernel<<<(Bn * Sn + 255) / 256, 256>>>(bva, score_buf);
    {
        dim3 grid(An / 128, Bn * Sn / 128);
        score_gemm_mma<<<grid, 256, score_smem>>>(enc_h, wae_h, ba_e, q_buf, va, score_buf);
    }

    // 4. softmax
    softmax_kernel<<<Bn, 256>>>(score_buf, out_attn);

    // 5. context -> xh0[:, 1024:2048]  (reads fp16 enc)
    {
        dim3 grid(Bn, En / 256);
        context_kernel<<<grid, 256>>>(enc_h, out_attn, xh0);
    }

    // 6. LSTM layer 0: gates = [x, h0[0]] @ [Wih0; Whh0]^T + biases
    gemm_nt_tc2<<<4 * Hn / 64, 128>>>(xh0, 3072, Wih0, Dn + En, Whh0,
                                      bih0, bhh0, gates_buf, 4 * Hn);
    lstm_pointwise<<<(Bn * Hn + 255) / 256, 256>>>(gates_buf, c0, out_h, out_c,
                                                   xh1, 2048);

    // 7. LSTM layer 1: gates = [h1, h0[1]] @ [Wih1; Whh1]^T + biases
    gemm_nt_tc2<<<4 * Hn / 64, 128>>>(xh1, 2048, Wih1, Hn, Whh1,
                                      bih1, bhh1, gates_buf, 4 * Hn);
    lstm_pointwise<<<(Bn * Hn + 255) / 256, 256>>>(gates_buf, c0 + Bn * Hn,
                                                   out_h + Bn * Hn, out_c + Bn * Hn,
                                                   nullptr, 0);

    // 8. logits = h2 @ Wout^T + bout
    gemm_nt_tc2<<<Vn / 64, 128>>>(out_h + Bn * Hn, Hn, Wout, Hn, nullptr,
                                  bout, nullptr, out_logits, Vn);
}

// round 15
// speedup vs baseline: 2.2691x; 1.1379x over previous
#include <cuda_runtime.h>
#include <cuda_bf16.h>
#include <cuda_fp16.h>

#define Bn 64
#define Sn 1024
#define Vn 32000
#define Dn 1024
#define Hn 1024
#define En 1024
#define An 1024

// ---------------- scratch (no allocs allowed) ----------------
__device__ float g_q[Bn * An];
__device__ float g_score[Bn * Sn];
__device__ float g_xh0[Bn * 3072];   // [embedded(1024), context(1024), h0[0](1024)]
__device__ float g_xh1[Bn * 2048];   // [h1(1024), h0[1](1024)]
__device__ float g_gates[Bn * 4 * Hn];
__device__ __half g_enc_h[(size_t)Bn * Sn * En];  // fp16 enc
__device__ __half g_wae_h[(size_t)An * En];       // fp16 Wa_e

// ---------------- helpers ----------------
__device__ __forceinline__ unsigned f2tf(float f) {
    unsigned u;
    asm("cvt.rna.tf32.f32 %0, %1;" : "=r"(u) : "f"(f));
    return u;
}

__device__ __forceinline__ uint4 cvt4(float4 v) {
    uint4 o;
    o.x = f2tf(v.x); o.y = f2tf(v.y); o.z = f2tf(v.z); o.w = f2tf(v.w);
    return o;
}

__device__ __forceinline__ void mma_tf32(float* c, const unsigned* a, const unsigned* b) {
    asm volatile(
        "mma.sync.aligned.m16n8k8.row.col.f32.tf32.tf32.f32 "
        "{%0,%1,%2,%3}, {%4,%5,%6,%7}, {%8,%9}, {%0,%1,%2,%3};"
        : "+f"(c[0]), "+f"(c[1]), "+f"(c[2]), "+f"(c[3])
        : "r"(a[0]), "r"(a[1]), "r"(a[2]), "r"(a[3]), "r"(b[0]), "r"(b[1]));
}

__device__ __forceinline__ void mma_f16(float* c, const unsigned* a, const unsigned* b) {
    asm volatile(
        "mma.sync.aligned.m16n8k16.row.col.f32.f16.f16.f32 "
        "{%0,%1,%2,%3}, {%4,%5,%6,%7}, {%8,%9}, {%0,%1,%2,%3};"
        : "+f"(c[0]), "+f"(c[1]), "+f"(c[2]), "+f"(c[3])
        : "r"(a[0]), "r"(a[1]), "r"(a[2]), "r"(a[3]), "r"(b[0]), "r"(b[1]));
}

__device__ __forceinline__ void ldsm4(unsigned* r, unsigned addr) {
    asm volatile("ldmatrix.sync.aligned.m8n8.x4.shared.b16 {%0,%1,%2,%3}, [%4];"
                 : "=r"(r[0]), "=r"(r[1]), "=r"(r[2]), "=r"(r[3]) : "r"(addr));
}

__device__ __forceinline__ void cp_async16(unsigned saddr, const void* gptr) {
    asm volatile("cp.async.ca.shared.global [%0], [%1], 16;" :: "r"(saddr), "l"(gptr));
}
__device__ __forceinline__ void cp_commit() { asm volatile("cp.async.commit_group;"); }

__device__ __forceinline__ unsigned smem_u32(const void* p) {
    unsigned a;
    asm("{ .reg .u64 t; cvta.to.shared.u64 t, %1; cvt.u32.u64 %0, t; }" : "=r"(a) : "l"(p));
    return a;
}

// ---------------- fp16 pre-convert ----------------
__global__ void f16_convert(const float* __restrict__ src, __half* __restrict__ dst) {
    size_t i = ((size_t)blockIdx.x * 256 + threadIdx.x) * 8;
    float4 v0 = *(const float4*)(src + i);
    float4 v1 = *(const float4*)(src + i + 4);
    __half2 h0 = __floats2half2_rn(v0.x, v0.y);
    __half2 h1 = __floats2half2_rn(v0.z, v0.w);
    __half2 h2 = __floats2half2_rn(v1.x, v1.y);
    __half2 h3 = __floats2half2_rn(v1.z, v1.w);
    uint4 o;
    o.x = *(unsigned*)&h0; o.y = *(unsigned*)&h1;
    o.z = *(unsigned*)&h2; o.w = *(unsigned*)&h3;
    *(uint4*)(dst + i) = o;
}

// ---------------- bias init for split-K GEMMs: C[m,n] = bias(+bias2) ----------------
__global__ void bias_init_kernel(float* __restrict__ C, const float* __restrict__ bias,
                                 const float* __restrict__ bias2, int N) {
    int i = blockIdx.x * 256 + threadIdx.x;
    if (i >= 64 * N) return;
    int n = i % N;
    float v = bias ? bias[n] : 0.f;
    if (bias2) v += bias2[n];
    C[i] = v;
}

// ---------------- embedding gather + h staging ----------------
__global__ void embed_kernel(const int* __restrict__ input_step,
                             const float* __restrict__ emb,
                             const float* __restrict__ h0,
                             float* __restrict__ xh0,
                             float* __restrict__ xh1) {
    int b = blockIdx.x;
    int row = input_step[b];
    const float* src = emb + (size_t)row * Dn;
    for (int d = threadIdx.x; d < Dn; d += blockDim.x) {
        xh0[(size_t)b * 3072 + d] = src[d];
        xh0[(size_t)b * 3072 + 2048 + d] = h0[b * Hn + d];
        xh1[(size_t)b * 2048 + 1024 + d] = h0[Bn * Hn + b * Hn + d];
    }
}

// ---------------- tf32 TC GEMM, split-K weights + optional split-K parallelism ----------------
// C[64,N] (+)= A[64,Ktot slice] @ [W1;W2]^T. grid = (N/64, ksplit).
// ksplit==1: C = acc + bias (+bias2). ksplit>1: atomicAdd(acc) into pre-inited C.
__global__ __launch_bounds__(128) void gemm_nt_tc2(
        const float* __restrict__ Amat, int Ktot,
        const float* __restrict__ W1, int K1, const float* __restrict__ W2,
        const float* __restrict__ bias, const float* __restrict__ bias2,
        float* __restrict__ Cmat, int N, int ksplit) {
    __shared__ char gsm[2][16384];
    unsigned sbase = smem_u32(gsm);

    int tid = threadIdx.x;
    int w = tid >> 5, lane = tid & 31, g = lane >> 2, tig = lane & 3;
    int n0 = blockIdx.x * 64;
    int mb = (w & 1) * 32;
    int nb = (w >> 1) * 32;
    int K2 = Ktot - K1;

    int kper = Ktot / ksplit;
    int kbeg = blockIdx.y * kper;
    int kend = kbeg + kper;

    int lr = tid >> 3;
    int lc16 = tid & 7;

    int rA = mb + (lane & 15);
    int akh = (lane >> 4) & 1;
    unsigned aRow0 = rA * 128, aRow1 = (rA + 16) * 128;
    int am = rA & 7;
    int rB = nb + ((lane >> 1) & 8) + (lane & 7);
    int bkh = (lane >> 3) & 1;
    unsigned bRow0 = rB * 128, bRow1 = (rB + 16) * 128;
    int bm = rB & 7;

    float acc[2][4][4];
#pragma unroll
    for (int mt = 0; mt < 2; mt++)
#pragma unroll
        for (int nf = 0; nf < 4; nf++)
#pragma unroll
            for (int r = 0; r < 4; r++) acc[mt][nf][r] = 0.f;

#define WROW(row, k) ((k) < K1 ? W1 + (size_t)(row) * K1 + (k) \
                               : W2 + (size_t)(row) * K2 + ((k) - K1))

    float4 aReg[4], wReg[4];
#pragma unroll
    for (int i = 0; i < 4; i++) {
        int row = lr + 16 * i;
        aReg[i] = *(const float4*)&Amat[(size_t)row * Ktot + kbeg + lc16 * 4];
        wReg[i] = *(const float4*)(WROW(n0 + row, kbeg) + lc16 * 4);
    }

    int st = 0;
    for (int k0 = kbeg; k0 < kend; k0 += 32) {
#pragma unroll
        for (int i = 0; i < 4; i++) {
            int row = lr + 16 * i;
            unsigned off = row * 128 + (unsigned)((lc16 ^ (row & 7)) << 4);
            *(uint4*)(gsm[st] + off) = cvt4(aReg[i]);
            *(uint4*)(gsm[st] + 8192 + off) = cvt4(wReg[i]);
        }
        __syncthreads();

        if (k0 + 32 < kend) {
#pragma unroll
            for (int i = 0; i < 4; i++) {
                int row = lr + 16 * i;
                aReg[i] = *(const float4*)&Amat[(size_t)row * Ktot + k0 + 32 + lc16 * 4];
                wReg[i] = *(const float4*)(WROW(n0 + row, k0 + 32) + lc16 * 4);
            }
        }

        unsigned Ab = sbase + st * 16384;
        unsigned Wb = Ab + 8192;
#pragma unroll
        for (int ks = 0; ks < 4; ks++) {
            unsigned a0[4], a1[4], b0[4], b1[4];
            unsigned acol = ((unsigned)(ks * 2 + akh) ^ am) << 4;
            unsigned bcol = ((unsigned)(ks * 2 + bkh) ^ bm) << 4;
            ldsm4(a0, Ab + aRow0 + acol);
            ldsm4(a1, Ab + aRow1 + acol);
            ldsm4(b0, Wb + bRow0 + bcol);
            ldsm4(b1, Wb + bRow1 + bcol);
            mma_tf32(acc[0][0], a0, b0);
            mma_tf32(acc[0][1], a0, b0 + 2);
            mma_tf32(acc[1][0], a1, b0);
            mma_tf32(acc[1][1], a1, b0 + 2);
            mma_tf32(acc[0][2], a0, b1);
            mma_tf32(acc[0][3], a0, b1 + 2);
            mma_tf32(acc[1][2], a1, b1);
            mma_tf32(acc[1][3], a1, b1 + 2);
        }
        __syncthreads();
        st ^= 1;
    }
#undef WROW

#pragma unroll
    for (int mt = 0; mt < 2; mt++) {
        int m0i = mb + mt * 16 + g;
        int m1i = m0i + 8;
#pragma unroll
        for (int nf = 0; nf < 4; nf++) {
            int n = n0 + nb + nf * 8 + 2 * tig;
            if (ksplit > 1) {
                atomicAdd(&Cmat[(size_t)m0i * N + n],     acc[mt][nf][0]);
                atomicAdd(&Cmat[(size_t)m0i * N + n + 1], acc[mt][nf][1]);
                atomicAdd(&Cmat[(size_t)m1i * N + n],     acc[mt][nf][2]);
                atomicAdd(&Cmat[(size_t)m1i * N + n + 1], acc[mt][nf][3]);
            } else {
                float badd0 = 0.f, badd1 = 0.f;
                if (bias)  { badd0 += bias[n];  badd1 += bias[n + 1]; }
                if (bias2) { badd0 += bias2[n]; badd1 += bias2[n + 1]; }
                Cmat[(size_t)m0i * N + n]     = acc[mt][nf][0] + badd0;
                Cmat[(size_t)m0i * N + n + 1] = acc[mt][nf][1] + badd1;
                Cmat[(size_t)m1i * N + n]     = acc[mt][nf][2] + badd0;
                Cmat[(size_t)m1i * N + n + 1] = acc[mt][nf][3] + badd1;
            }
        }
    }
}

// ---------------- score init ----------------
__global__ void score_init_kernel(const float* __restrict__ bva, float* __restrict__ score) {
    int i = blockIdx.x * blockDim.x + threadIdx.x;
    if (i < Bn * Sn) score[i] = bva[0];
}

// ---------------- fused attention score GEMM (fp16 m16n8k16, wide warp tiles) ----------------
// BM=128, BN=128, BK=64 fp16. 256 threads = 8 warps (4m x 2n), warp tile 32x64.
// 3-stage cp.async pipeline; rows of 64 fp16 = 128B, XOR swizzle.
__global__ __launch_bounds__(256) void score_gemm_mma(
        const __half* __restrict__ enc_h, const __half* __restrict__ wae_h,
        const float* __restrict__ ba_e, const float* __restrict__ q,
        const float* __restrict__ va, float* __restrict__ score) {
    extern __shared__ char smem_raw[];
    unsigned sbase = smem_u32(smem_raw);
    const unsigned STAGE = 32768;  // A 16KB + W 16KB (fp16)
    float* qb  = (float*)(smem_raw + 3 * STAGE);
    float* vas = qb + 128;

    int tid = threadIdx.x;
    int w = tid >> 5, lane = tid & 31, g = lane >> 2, tig = lane & 3;
    int n0 = blockIdx.x * 128;
    int m0 = blockIdx.y * 128;
    int b = m0 >> 10;
    int mb = (w >> 1) * 32;    // 4 m-warps
    int nb = (w & 1) * 64;     // 2 n-warps, 64 cols each

    if (tid < 128) {
        qb[tid]  = q[b * An + n0 + tid] + ba_e[n0 + tid];
        vas[tid] = va[n0 + tid];
    }

    int crow = tid >> 3;    // 0..31
    int ccol = tid & 7;
    const __half* encp = enc_h + (size_t)m0 * En;
    const __half* waep = wae_h + (size_t)n0 * En;

    int rA = mb + (lane & 15);
    int akh = (lane >> 4) & 1;
    unsigned aRow0 = rA * 128, aRow1 = (rA + 16) * 128;
    int am = rA & 7;
    int rBb = ((lane >> 1) & 8) + (lane & 7);
    int bkh = (lane >> 3) & 1;
    unsigned bRow[4];
    int bm[4];
#pragma unroll
    for (int j = 0; j < 4; j++) {
        int r = nb + 16 * j + rBb;
        bRow[j] = r * 128;
        bm[j] = r & 7;
    }

    float acc[2][8][4];
#pragma unroll
    for (int mt = 0; mt < 2; mt++)
#pragma unroll
        for (int nf = 0; nf < 8; nf++)
#pragma unroll
            for (int r = 0; r < 4; r++) acc[mt][nf][r] = 0.f;

#define PREFETCH(st, k0)                                                          \
    do {                                                                          \
        unsigned Ad = sbase + (st) * STAGE;                                       \
        unsigned Wd = Ad + 16384;                                                 \
        _Pragma("unroll")                                                         \
        for (int i = 0; i < 4; i++) {                                             \
            int row = crow + i * 32;                                              \
            cp_async16(Ad + row * 128 + ((ccol ^ (row & 7)) << 4),                \
                       encp + (size_t)row * En + (k0) + ccol * 8);                \
        }                                                                         \
        _Pragma("unroll")                                                         \
        for (int i = 0; i < 4; i++) {                                             \
            int row = crow + i * 32;                                              \
            cp_async16(Wd + row * 128 + ((ccol ^ (row & 7)) << 4),                \
                       waep + (size_t)row * En + (k0) + ccol * 8);                \
        }                                                                         \
        cp_commit();                                                              \
    } while (0)

    PREFETCH(0, 0);
    PREFETCH(1, 64);

    const int NT = En / 64;  // 16 iterations
    int st = 0;
    for (int it = 0; it < NT; it++) {
        if (it == NT - 1) asm volatile("cp.async.wait_group 0;");
        else              asm volatile("cp.async.wait_group 1;");
        __syncthreads();

        unsigned Ab = sbase + st * STAGE;
        unsigned Wb = Ab + 16384;
#pragma unroll
        for (int ks = 0; ks < 4; ks++) {
            unsigned a0[4], a1[4];
            unsigned acol = ((unsigned)(ks * 2 + akh) ^ am) << 4;
            ldsm4(a0, Ab + aRow0 + acol);
            ldsm4(a1, Ab + aRow1 + acol);
#pragma unroll
            for (int j = 0; j < 4; j++) {
                unsigned bf[4];
                unsigned bcol = ((unsigned)(ks * 2 + bkh) ^ bm[j]) << 4;
                ldsm4(bf, Wb + bRow[j] + bcol);
                mma_f16(acc[0][2 * j],     a0, bf);
                mma_f16(acc[0][2 * j + 1], a0, bf + 2);
                mma_f16(acc[1][2 * j],     a1, bf);
                mma_f16(acc[1][2 * j + 1], a1, bf + 2);
            }
        }

        int pf = it + 2;
        if (pf < NT) PREFETCH(pf % 3, pf * 64);
        st = (st + 1 == 3) ? 0 : st + 1;
    }
#undef PREFETCH

    // epilogue: tanh + va-weighted row reduction
#pragma unroll
    for (int mt = 0; mt < 2; mt++) {
        float sumlo = 0.f, sumhi = 0.f;
#pragma unroll
        for (int nf = 0; nf < 8; nf++) {
            int nl = nb + nf * 8 + 2 * tig;
            float q0 = qb[nl], q1 = qb[nl + 1];
            float v0 = vas[nl], v1 = vas[nl + 1];
            sumlo += v0 * tanhf(acc[mt][nf][0] + q0) + v1 * tanhf(acc[mt][nf][1] + q1);
            sumhi += v0 * tanhf(acc[mt][nf][2] + q0) + v1 * tanhf(acc[mt][nf][3] + q1);
        }
        sumlo += __shfl_xor_sync(0xffffffffu, sumlo, 1);
        sumlo += __shfl_xor_sync(0xffffffffu, sumlo, 2);
        sumhi += __shfl_xor_sync(0xffffffffu, sumhi, 1);
        sumhi += __shfl_xor_sync(0xffffffffu, sumhi, 2);
        if (tig == 0) {
            int r = m0 + mb + mt * 16 + g;
            atomicAdd(&score[r], sumlo);
            atomicAdd(&score[r + 8], sumhi);
        }
    }
}

// ---------------- softmax ----------------
__global__ void softmax_kernel(const float* __restrict__ score, float* __restrict__ attn) {
    __shared__ float sh[Sn];
    __shared__ float red[256];
    int b = blockIdx.x;
    int tid = threadIdx.x;

    float lmax = -3.4e38f;
    for (int s = tid; s < Sn; s += 256) {
        float v = score[b * Sn + s];
        sh[s] = v;
        lmax = fmaxf(lmax, v);
    }
    red[tid] = lmax;
    __syncthreads();
    for (int off = 128; off > 0; off >>= 1) {
        if (tid < off) red[tid] = fmaxf(red[tid], red[tid + off]);
        __syncthreads();
    }
    float m = red[0];
    __syncthreads();

    float lsum = 0.f;
    for (int s = tid; s < Sn; s += 256) {
        float e = expf(sh[s] - m);
        sh[s] = e;
        lsum += e;
    }
    red[tid] = lsum;
    __syncthreads();
    for (int off = 128; off > 0; off >>= 1) {
        if (tid < off) red[tid] += red[tid + off];
        __syncthreads();
    }
    float inv = 1.f / red[0];
    __syncthreads();

    for (int s = tid; s < Sn; s += 256) attn[b * Sn + s] = sh[s] * inv;
}

// ---------------- context = attn @ enc_h (fp16 enc, fp32 accumulate) ----------------
__global__ void context_kernel(const __half* __restrict__ enc_h,
                               const float* __restrict__ attn,
                               float* __restrict__ xh0) {
    __shared__ float w[Sn];
    int b = blockIdx.x;
    int e = blockIdx.y * 256 + threadIdx.x;
    for (int s = threadIdx.x; s < Sn; s += 256) w[s] = attn[b * Sn + s];
    __syncthreads();
    const __half* ep = enc_h + (size_t)b * Sn * En + e;
    float acc = 0.f;
#pragma unroll 8
    for (int s = 0; s < Sn; s++) acc += w[s] * __half2float(ep[(size_t)s * En]);
    xh0[(size_t)b * 3072 + 1024 + e] = acc;
}

// ---------------- LSTM pointwise ----------------
__global__ void lstm_pointwise(const float* __restrict__ gates,
                               const float* __restrict__ cprev,
                               float* __restrict__ hout,
                               float* __restrict__ cout,
                               float* __restrict__ hcopy, int hstride) {
    int idx = blockIdx.x * 256 + threadIdx.x;
    if (idx >= Bn * Hn) return;
    int b = idx >> 10;
    int h = idx & 1023;
    const float* g = gates + (size_t)b * 4 * Hn;
    float ig = 1.f / (1.f + expf(-g[h]));
    float fg = 1.f / (1.f + expf(-g[Hn + h]));
    float gg = tanhf(g[2 * Hn + h]);
    float og = 1.f / (1.f + expf(-g[3 * Hn + h]));
    float c = fg * cprev[idx] + ig * gg;
    float hv = og * tanhf(c);
    hout[idx] = hv;
    cout[idx] = c;
    if (hcopy) hcopy[(size_t)b * hstride + h] = hv;
}

// ---------------- launcher ----------------
extern "C" void kernel_launch(void* const* d_in, const int* in_sizes, int n_in,
                              void* d_out, int out_size) {
    const int*   input_step = (const int*)d_in[0];
    const float* h0    = (const float*)d_in[1];
    const float* c0    = (const float*)d_in[2];
    const float* enc   = (const float*)d_in[3];
    const float* emb   = (const float*)d_in[4];
    const float* Wa_h  = (const float*)d_in[5];
    const float* ba_h  = (const float*)d_in[6];
    const float* Wa_e  = (const float*)d_in[7];
    const float* ba_e  = (const float*)d_in[8];
    const float* va    = (const float*)d_in[9];
    const float* bva   = (const float*)d_in[10];
    const float* Wih0  = (const float*)d_in[11];
    const float* Whh0  = (const float*)d_in[12];
    const float* bih0  = (const float*)d_in[13];
    const float* bhh0  = (const float*)d_in[14];
    const float* Wih1  = (const float*)d_in[15];
    const float* Whh1  = (const float*)d_in[16];
    const float* bih1  = (const float*)d_in[17];
    const float* bhh1  = (const float*)d_in[18];
    const float* Wout  = (const float*)d_in[19];
    const float* bout  = (const float*)d_in[20];

    float* out = (float*)d_out;
    float* out_logits = out;
    float* out_h      = out_logits + Bn * Vn;
    float* out_c      = out_h + 2 * Bn * Hn;
    float* out_attn   = out_c + 2 * Bn * Hn;

    float* q_buf;     cudaGetSymbolAddress((void**)&q_buf, g_q);
    float* score_buf; cudaGetSymbolAddress((void**)&score_buf, g_score);
    float* xh0;       cudaGetSymbolAddress((void**)&xh0, g_xh0);
    float* xh1;       cudaGetSymbolAddress((void**)&xh1, g_xh1);
    float* gates_buf; cudaGetSymbolAddress((void**)&gates_buf, g_gates);
    __half* enc_h;    cudaGetSymbolAddress((void**)&enc_h, g_enc_h);
    __half* wae_h;    cudaGetSymbolAddress((void**)&wae_h, g_wae_h);

    const int score_smem = 3 * 32768 + 1024;  // 99328
    cudaFuncSetAttribute(score_gemm_mma, cudaFuncAttributeMaxDynamicSharedMemorySize,
                         score_smem);

    // 0. pre-convert enc and Wa_e to fp16
    f16_convert<<<(Bn * Sn * En) / 2048, 256>>>(enc, enc_h);
    f16_convert<<<(An * En) / 2048, 256>>>(Wa_e, wae_h);

    // 1. embedding gather + h0 staging
    embed_kernel<<<Bn, 256>>>(input_step, emb, h0, xh0, xh1);

    // 2. q = h0[1] @ Wa_h^T + ba_h  (split-K x4)
    bias_init_kernel<<<(64 * An + 255) / 256, 256>>>(q_buf, ba_h, nullptr, An);
    {
        dim3 grid(An / 64, 4);
        gemm_nt_tc2<<<grid, 128>>>(h0 + Bn * Hn, Hn, Wa_h, Hn, nullptr,
                                   nullptr, nullptr, q_buf, An, 4);
    }

    // 3. fused fp16 score GEMM
    score_init_kernel<<<(Bn * Sn + 255) / 256, 256>>>(bva, score_buf);
    {
        dim3 grid(An / 128, Bn * Sn / 128);
        score_gemm_mma<<<grid, 256, score_smem>>>(enc_h, wae_h, ba_e, q_buf, va, score_buf);
    }

    // 4. softmax
    softmax_kernel<<<Bn, 256>>>(score_buf, out_attn);

    // 5. context -> xh0[:, 1024:2048]  (reads fp16 enc)
    {
        dim3 grid(Bn, En / 256);
        context_kernel<<<grid, 256>>>(enc_h, out_attn, xh0);
    }

    // 6. LSTM layer 0: gates = [x, h0[0]] @ [Wih0; Whh0]^T + biases  (split-K x3)
    bias_init_kernel<<<(64 * 4 * Hn + 255) / 256, 256>>>(gates_buf, bih0, bhh0, 4 * Hn);
    {
        dim3 grid(4 * Hn / 64, 3);
        gemm_nt_tc2<<<grid, 128>>>(xh0, 3072, Wih0, Dn + En, Whh0,
                                   nullptr, nullptr, gates_buf, 4 * Hn, 3);
    }
    lstm_pointwise<<<(Bn * Hn + 255) / 256, 256>>>(gates_buf, c0, out_h, out_c,
                                                   xh1, 2048);

    // 7. LSTM layer 1: gates = [h1, h0[1]] @ [Wih1; Whh1]^T + biases  (split-K x2)
    bias_init_kernel<<<(64 * 4 * Hn + 255) / 256, 256>>>(gates_buf, bih1, bhh1, 4 * Hn);
    {
        dim3 grid(4 * Hn / 64, 2);
        gemm_nt_tc2<<<grid, 128>>>(xh1, 2048, Wih1, Hn, Whh1,
                                   nullptr, nullptr, gates_buf, 4 * Hn, 2);
    }
    lstm_pointwise<<<(Bn * Hn + 255) / 256, 256>>>(gates_buf, c0 + Bn * Hn,
                                                   out_h + Bn * Hn, out_c + Bn * Hn,
                                                   nullptr, 0);

    // 8. logits = h2 @ Wout^T + bout (no split; grid already 500)
    {
        dim3 grid(Vn / 64, 1);
        gemm_nt_tc2<<<grid, 128>>>(out_h + Bn * Hn, Hn, Wout, Hn, nullptr,
                                   bout, nullptr, out_logits, Vn, 1);
    }
}